// round 8
// baseline (speedup 1.0000x reference)
#include <cuda_runtime.h>
#include <math.h>

#define BB 32
#define TT 512
#define TT1 513
#define SD 256
#define HD 512
#define BT (BB*TT)
#define MS (BT*SD)
#define MT (BT*TT)
#define NB 64

__device__ __align__(128) float g_st[MS], g_se[MS], g_tp[MS], g_tc[MS], g_gg[MS];
__device__ __align__(128) float g_A[MT], g_L[MT], g_Li[MT], g_cat[MT], g_cat2[MT];
__device__ __align__(128) float g_cs[BT], g_ar[BT], g_dg[BT];
__device__ __align__(128) int   g_piv[BT];

// ---------------- elementwise ----------------
__global__ void split_k(const float* __restrict__ x) {
  int idx = blockIdx.x*blockDim.x + threadIdx.x;
  int c = idx & 511; int bt = idx >> 9;
  const float* xp = x + (size_t)bt*HD;
  if (c < SD) g_se[(size_t)bt*SD + c] = xp[c + ((c >= 128) ? 128 : 0)];
  else { int cc = c - SD; g_st[(size_t)bt*SD + cc] = xp[cc + 128 + ((cc >= 128) ? 128 : 0)]; }
}

__global__ void root_k(const float* __restrict__ wr, const int* __restrict__ seq) {
  int g = blockIdx.x*blockDim.x + threadIdx.x;
  int w = g >> 5, lane = g & 31;
  if (w >= BT) return;
  const float* s = g_st + (size_t)w*SD;
  float acc = 0.f;
  for (int c = lane; c < SD; c += 32) acc += s[c]*wr[c];
  for (int o = 16; o > 0; o >>= 1) acc += __shfl_down_sync(0xffffffffu, acc, o);
  if (lane == 0) {
    int b = w >> 9, t = w & 511;
    g_ar[w] = (t < seq[b]) ? expf(acc) : 0.0f;
  }
}

__global__ void colsum_k() {
  int b = blockIdx.x, j = threadIdx.x;
  const float* a = g_A + (size_t)b*TT*TT;
  float s = 0.f;
  for (int i = 0; i < TT; ++i) s += a[(size_t)i*TT + j];
  g_cs[b*TT + j] = s;
}

__global__ void buildL_k(const int* __restrict__ seq) {
  int idx = blockIdx.x*blockDim.x + threadIdx.x;
  int j = idx & 511, i = (idx >> 9) & 511, b = idx >> 18;
  float v;
  if (i == 0) v = g_ar[b*TT + j];
  else {
    v = -g_A[idx];
    if (i == j) v += g_cs[b*TT + j] + ((j >= seq[b]) ? 1.0f : 0.0f);
  }
  g_L[idx] = v;
}

// ---------------- blocked Gauss-Jordan inverse (NB=64, partial pivoting) ----------------
__global__ __launch_bounds__(1024) void panel_k(int k0) {
  extern __shared__ float panel[];  // 512 x 65
  __shared__ float colM[TT];
  __shared__ float redv[32]; __shared__ int redi[32];
  __shared__ float sPinv; __shared__ int sIr;
  __shared__ int spiv[NB];
  int b = blockIdx.x, tid = threadIdx.x;
  float* a = g_L + (size_t)b*TT*TT;
  for (int idx = tid; idx < TT*NB; idx += 1024) {
    int i = idx >> 6, c = idx & 63;
    panel[i*65+c] = a[(size_t)i*TT + k0 + c];
  }
  __syncthreads();
  for (int kk = 0; kk < NB; ++kk) {
    int k = k0 + kk;
    float v = -1.0f; int ix = tid;
    if (tid < TT && tid >= k) v = fabsf(panel[tid*65+kk]);
    for (int o = 16; o > 0; o >>= 1) {
      float v2 = __shfl_down_sync(0xffffffffu, v, o);
      int   i2 = __shfl_down_sync(0xffffffffu, ix, o);
      if (v2 > v) { v = v2; ix = i2; }
    }
    if ((tid & 31) == 0) { redv[tid>>5] = v; redi[tid>>5] = ix; }
    __syncthreads();
    if (tid == 0) {
      float bv = redv[0]; int bi = redi[0];
      for (int w = 1; w < 32; ++w) if (redv[w] > bv) { bv = redv[w]; bi = redi[w]; }
      sIr = bi; spiv[kk] = bi; g_piv[b*TT+k] = bi;
    }
    __syncthreads();
    int ir = sIr;
    if (ir != k && tid < NB) {
      float t = panel[k*65+tid]; panel[k*65+tid] = panel[ir*65+tid]; panel[ir*65+tid] = t;
    }
    __syncthreads();
    if (tid == 0) sPinv = 1.0f / panel[k*65+kk];
    __syncthreads();
    float pinv = sPinv;
    if (tid < NB) {
      float val = panel[k*65+tid];
      if (tid == kk) val = 1.0f;
      panel[k*65+tid] = val * pinv;
    } else if (tid >= 128 && tid < 128+TT) {
      colM[tid-128] = panel[(tid-128)*65+kk];
    }
    __syncthreads();
    for (int idx = tid; idx < TT*NB; idx += 1024) {
      int i = idx >> 6, c = idx & 63;
      if (i == k) continue;
      float m  = colM[i];
      float rk = panel[k*65+c];
      float cur = (c == kk) ? 0.0f : panel[i*65+c];
      panel[i*65+c] = cur - m*rk;
    }
    __syncthreads();
  }
  for (int s = 0; s < NB; ++s) {
    int k = k0 + s, ir = spiv[s];
    if (ir != k && tid < 128) {
      float4* rk = (float4*)(a + (size_t)k*TT);
      float4* rr = (float4*)(a + (size_t)ir*TT);
      float4 t = rk[tid]; rk[tid] = rr[tid]; rr[tid] = t;
    }
    __syncthreads();
  }
  for (int idx = tid; idx < TT*NB; idx += 1024) {
    int i = idx >> 6, c = idx & 63;
    a[(size_t)i*TT + k0 + c] = panel[i*65+c];
  }
}

__global__ __launch_bounds__(1024) void update_k(int k0) {
  extern __shared__ float sm[];
  float* Ps = sm;           // 512 x 65
  float* Rs = sm + TT*65;   // 64 x 132
  int b = blockIdx.y, tid = threadIdx.x;
  int jbase = blockIdx.x * 128;
  float* a = g_L + (size_t)b*TT*TT;
  for (int idx = tid; idx < TT*NB; idx += 1024) {
    int i = idx >> 6, c = idx & 63;
    Ps[i*65+c] = a[(size_t)i*TT + k0 + c];
  }
  for (int idx = tid; idx < NB*128; idx += 1024) {
    int k = idx >> 7, c = idx & 127;
    Rs[k*132+c] = a[(size_t)(k0+k)*TT + jbase + c];
  }
  __syncthreads();
  int tx = tid & 31, ty = tid >> 5;
  int j = jbase + tx*4;
  if (j >= k0 && j < k0 + NB) return;
  for (int r = 0; r < 4; ++r) {
    int i0 = r*128 + ty*4;
    float acc[4][4] = {};
#pragma unroll 8
    for (int k = 0; k < NB; ++k) {
      float4 rv = *(const float4*)(Rs + k*132 + tx*4);
      float p0 = Ps[(i0+0)*65+k], p1 = Ps[(i0+1)*65+k];
      float p2 = Ps[(i0+2)*65+k], p3 = Ps[(i0+3)*65+k];
      acc[0][0]+=p0*rv.x; acc[0][1]+=p0*rv.y; acc[0][2]+=p0*rv.z; acc[0][3]+=p0*rv.w;
      acc[1][0]+=p1*rv.x; acc[1][1]+=p1*rv.y; acc[1][2]+=p1*rv.z; acc[1][3]+=p1*rv.w;
      acc[2][0]+=p2*rv.x; acc[2][1]+=p2*rv.y; acc[2][2]+=p2*rv.z; acc[2][3]+=p2*rv.w;
      acc[3][0]+=p3*rv.x; acc[3][1]+=p3*rv.y; acc[3][2]+=p3*rv.z; acc[3][3]+=p3*rv.w;
    }
#pragma unroll
    for (int q = 0; q < 4; ++q) {
      int i = i0 + q;
      float4 res;
      if (i >= k0 && i < k0 + NB) res = make_float4(0.f,0.f,0.f,0.f);
      else res = *(const float4*)(a + (size_t)i*TT + j);
      res.x += acc[q][0]; res.y += acc[q][1]; res.z += acc[q][2]; res.w += acc[q][3];
      *(float4*)(a + (size_t)i*TT + j) = res;
    }
  }
}

__global__ __launch_bounds__(1024) void gather_k() {
  __shared__ int arr[TT];
  int b = blockIdx.x, tid = threadIdx.x;
  if (tid == 0) {
    for (int j = 0; j < TT; ++j) arr[j] = j;
    for (int l = TT-1; l >= 0; --l) {
      int p = g_piv[b*TT + l];
      if (p != l) { int t = arr[l]; arr[l] = arr[p]; arr[p] = t; }
    }
  }
  __syncthreads();
  const float* a = g_L + (size_t)b*TT*TT;
  float* o = g_Li + (size_t)b*TT*TT;
  for (int idx = tid; idx < TT*TT; idx += 1024) {
    int i = idx >> 9, j = idx & 511;
    o[idx] = a[(size_t)i*TT + arr[j]];
  }
}

__global__ void diag_k(float* __restrict__ out2) {
  int b = blockIdx.x, j = threadIdx.x;
  const float* L = g_Li + (size_t)b*TT*TT;
  g_dg[b*TT + j] = L[(size_t)j*TT + j];
  out2[(size_t)b*TT1*TT + j] = g_ar[b*TT + j] * L[(size_t)j*TT];
}

__global__ __launch_bounds__(1024) void pij_k(float* __restrict__ out2) {
  __shared__ float Ts[32][33];
  int b = blockIdx.z;
  int i0 = blockIdx.y*32, j0 = blockIdx.x*32;
  int tx = threadIdx.x, ty = threadIdx.y;
  const float* L = g_Li + (size_t)b*TT*TT;
  Ts[ty][tx] = L[(size_t)(j0+ty)*TT + i0 + tx];
  __syncthreads();
  int i = i0 + ty, j = j0 + tx;
  float av  = g_A[(size_t)b*TT*TT + (size_t)i*TT + j];
  float dj  = (j > 0) ? g_dg[b*TT + j] : 0.0f;
  float lji = (i > 0) ? Ts[tx][ty] : 0.0f;
  out2[(size_t)b*TT1*TT + (size_t)(i+1)*TT + j] = av * (dj - lji);
}

__global__ void addroot_k(const float* __restrict__ re, const float* __restrict__ out2) {
  int idx = blockIdx.x*blockDim.x + threadIdx.x;
  int c = idx & 255, bi = idx >> 8;
  int b = bi >> 9, i = bi & 511;
  float pr = out2[(size_t)b*TT1*TT + i];
  g_cat[(size_t)bi*HD + c] += pr * re[c];
}

// ---------------- SIMT tiled GEMM (fp32-exact path) ----------------
// MODE 0: C = A(MxK)*B(NxK)^T ; MODE 1: C = A(MxK)*B(KxN)
// act: 0 none, 1 tanh, 3 exp+tree-mask (uses seq, global i/j)
#define BKD 16
#define PADW 68
template<int MODE>
__global__ __launch_bounds__(256)
void gemm_k(const float* __restrict__ A, int lda, long long sA,
            const float* __restrict__ B, int ldb, long long sB,
            float* __restrict__ C, int ldc, long long sC,
            int K, const float* __restrict__ bias, int act, const int* __restrict__ seq)
{
  __shared__ __align__(16) float As[BKD*PADW];
  __shared__ __align__(16) float Bs[BKD*PADW];
  const int tid = threadIdx.x;
  const int tx = tid & 15, ty = tid >> 4;
  const int m0 = blockIdx.y*64, n0 = blockIdx.x*64;
  const float* Ab = A + (size_t)blockIdx.z*sA;
  const float* Bb = B + (size_t)blockIdx.z*sB;
  float* Cb = C + (size_t)blockIdx.z*sC;
  const int r4 = tid >> 2, k4 = (tid & 3)*4;
  const int k16 = tid >> 4, c16 = (tid & 15)*4;
  float acc[4][4] = {};
  for (int k0 = 0; k0 < K; k0 += BKD) {
    float4 aL = *(const float4*)(Ab + (size_t)(m0+r4)*lda + k0 + k4);
    float4 bL;
    if (MODE == 0) bL = *(const float4*)(Bb + (size_t)(n0+r4)*ldb + k0 + k4);
    else           bL = *(const float4*)(Bb + (size_t)(k0+k16)*ldb + n0 + c16);
    __syncthreads();
    As[(k4+0)*PADW + r4] = aL.x; As[(k4+1)*PADW + r4] = aL.y;
    As[(k4+2)*PADW + r4] = aL.z; As[(k4+3)*PADW + r4] = aL.w;
    if (MODE == 0) {
      Bs[(k4+0)*PADW + r4] = bL.x; Bs[(k4+1)*PADW + r4] = bL.y;
      Bs[(k4+2)*PADW + r4] = bL.z; Bs[(k4+3)*PADW + r4] = bL.w;
    } else *(float4*)(Bs + k16*PADW + c16) = bL;
    __syncthreads();
#pragma unroll
    for (int kk = 0; kk < BKD; ++kk) {
      float4 av = *(const float4*)(As + kk*PADW + ty*4);
      float4 bv = *(const float4*)(Bs + kk*PADW + tx*4);
      acc[0][0] += av.x*bv.x; acc[0][1] += av.x*bv.y; acc[0][2] += av.x*bv.z; acc[0][3] += av.x*bv.w;
      acc[1][0] += av.y*bv.x; acc[1][1] += av.y*bv.y; acc[1][2] += av.y*bv.z; acc[1][3] += av.y*bv.w;
      acc[2][0] += av.z*bv.x; acc[2][1] += av.z*bv.y; acc[2][2] += av.z*bv.z; acc[2][3] += av.z*bv.w;
      acc[3][0] += av.w*bv.x; acc[3][1] += av.w*bv.y; acc[3][2] += av.w*bv.z; acc[3][3] += av.w*bv.w;
    }
  }
  float4 bb = make_float4(0.f,0.f,0.f,0.f);
  if (bias) { const float* bp = bias + n0 + tx*4; bb = make_float4(bp[0],bp[1],bp[2],bp[3]); }
  int len = (act == 3) ? seq[blockIdx.z] : 0;
#pragma unroll
  for (int i = 0; i < 4; ++i) {
    float4 v = make_float4(acc[i][0]+bb.x, acc[i][1]+bb.y, acc[i][2]+bb.z, acc[i][3]+bb.w);
    if (act == 1) { v.x=tanhf(v.x); v.y=tanhf(v.y); v.z=tanhf(v.z); v.w=tanhf(v.w); }
    else if (act == 3) {
      int gi = m0 + ty*4 + i, gj = n0 + tx*4;
      float* pv = (float*)&v;
#pragma unroll
      for (int q = 0; q < 4; ++q) {
        int j = gj + q;
        pv[q] = (gi != j && gi < len && j < len) ? expf(pv[q]) : 0.0f;
      }
    }
    *(float4*)(Cb + (size_t)(m0+ty*4+i)*ldc + n0 + tx*4) = v;
  }
}

// ---------------- tf32 tensor-core GEMM (out1 path) ----------------
// MODE 0: C = A(MxK)*B(NxK)^T ; MODE 1: C = A(MxK)*B(KxN) ; MODE 2: C = A(KxM)^T*B(KxN)
// CTA tile 128x64, 8 warps (4m x 2n), warp tile 32x32, mma m16n8k8.
#define TFA 136
#define TFB 72
__device__ __forceinline__ float f2tf(float f) {
  unsigned u; asm("cvt.rna.tf32.f32 %0, %1;" : "=r"(u) : "f"(f));
  return __uint_as_float(u);
}
template<int MODE>
__global__ __launch_bounds__(256)
void tgemm_k(const float* __restrict__ A, int lda, long long sA,
             const float* __restrict__ B, int ldb, long long sB,
             float* __restrict__ C, int ldc, long long sC,
             int K, const float* __restrict__ bias, int act)
{
  __shared__ __align__(16) float As[16*TFA];
  __shared__ __align__(16) float Bs[16*TFB];
  int tid = threadIdx.x;
  int m0 = blockIdx.y*128, n0 = blockIdx.x*64;
  const float* Ab = A + (size_t)blockIdx.z*sA;
  const float* Bb = B + (size_t)blockIdx.z*sB;
  float* Cb = C + (size_t)blockIdx.z*sC;
  int warp = tid>>5, lane = tid&31;
  int wm = (warp&3)*32, wn = (warp>>2)*32;
  int g = lane>>2, la3 = lane&3;
  float acc[2][4][4];
#pragma unroll
  for(int a=0;a<2;a++)
#pragma unroll
    for(int b=0;b<4;b++)
#pragma unroll
      for(int c=0;c<4;c++) acc[a][b][c]=0.f;

  for (int k0 = 0; k0 < K; k0 += 16) {
    __syncthreads();
#pragma unroll
    for (int q = 0; q < 2; ++q) {
      int idx = tid + q*256;
      if (MODE == 2) {
        int kr = idx >> 5, c4 = (idx & 31)*4;
        float4 v = *(const float4*)(Ab + (size_t)(k0+kr)*lda + m0 + c4);
        v.x = f2tf(v.x); v.y = f2tf(v.y); v.z = f2tf(v.z); v.w = f2tf(v.w);
        *(float4*)(As + kr*TFA + c4) = v;
      } else {
        int r = idx >> 2, c4 = (idx & 3)*4;
        float4 v = *(const float4*)(Ab + (size_t)(m0+r)*lda + k0 + c4);
        As[(c4+0)*TFA + r] = f2tf(v.x); As[(c4+1)*TFA + r] = f2tf(v.y);
        As[(c4+2)*TFA + r] = f2tf(v.z); As[(c4+3)*TFA + r] = f2tf(v.w);
      }
    }
    {
      int idx = tid;
      if (MODE == 0) {
        int r = idx >> 2, c4 = (idx & 3)*4;
        float4 v = *(const float4*)(Bb + (size_t)(n0+r)*ldb + k0 + c4);
        Bs[(c4+0)*TFB + r] = f2tf(v.x); Bs[(c4+1)*TFB + r] = f2tf(v.y);
        Bs[(c4+2)*TFB + r] = f2tf(v.z); Bs[(c4+3)*TFB + r] = f2tf(v.w);
      } else {
        int kr = idx >> 4, c4 = (idx & 15)*4;
        float4 v = *(const float4*)(Bb + (size_t)(k0+kr)*ldb + n0 + c4);
        v.x = f2tf(v.x); v.y = f2tf(v.y); v.z = f2tf(v.z); v.w = f2tf(v.w);
        *(float4*)(Bs + kr*TFB + c4) = v;
      }
    }
    __syncthreads();
#pragma unroll
    for (int ks = 0; ks < 2; ++ks) {
      int kb = ks*8;
      unsigned af[2][4];
#pragma unroll
      for (int mt = 0; mt < 2; ++mt) {
        const float* ap = As + (kb + la3)*TFA + wm + mt*16 + g;
        af[mt][0] = __float_as_uint(ap[0]);
        af[mt][1] = __float_as_uint(ap[8]);
        af[mt][2] = __float_as_uint(ap[4*TFA]);
        af[mt][3] = __float_as_uint(ap[4*TFA + 8]);
      }
#pragma unroll
      for (int nt = 0; nt < 4; ++nt) {
        const float* bp = Bs + (kb + la3)*TFB + wn + nt*8 + g;
        unsigned b0 = __float_as_uint(bp[0]);
        unsigned b1 = __float_as_uint(bp[4*TFB]);
#pragma unroll
        for (int mt = 0; mt < 2; ++mt) {
          asm volatile("mma.sync.aligned.m16n8k8.row.col.f32.tf32.tf32.f32 "
            "{%0,%1,%2,%3}, {%4,%5,%6,%7}, {%8,%9}, {%0,%1,%2,%3};"
            : "+f"(acc[mt][nt][0]), "+f"(acc[mt][nt][1]),
              "+f"(acc[mt][nt][2]), "+f"(acc[mt][nt][3])
            : "r"(af[mt][0]), "r"(af[mt][1]), "r"(af[mt][2]), "r"(af[mt][3]),
              "r"(b0), "r"(b1));
        }
      }
    }
  }
#pragma unroll
  for (int mt = 0; mt < 2; ++mt) {
    int mrow = m0 + wm + mt*16 + g;
#pragma unroll
    for (int nt = 0; nt < 4; ++nt) {
      int ncol = n0 + wn + nt*8 + la3*2;
      float b0v = 0.f, b1v = 0.f;
      if (bias) { b0v = bias[ncol]; b1v = bias[ncol+1]; }
      float v0 = acc[mt][nt][0] + b0v, v1 = acc[mt][nt][1] + b1v;
      float v2 = acc[mt][nt][2] + b0v, v3 = acc[mt][nt][3] + b1v;
      if (act == 2) {
        v0 = v0>=0.f?v0:0.01f*v0; v1 = v1>=0.f?v1:0.01f*v1;
        v2 = v2>=0.f?v2:0.01f*v2; v3 = v3>=0.f?v3:0.01f*v3;
      }
      *(float2*)(Cb + (size_t)mrow*ldc + ncol) = make_float2(v0, v1);
      *(float2*)(Cb + (size_t)(mrow+8)*ldc + ncol) = make_float2(v2, v3);
    }
  }
}

// ---------------- launch ----------------
extern "C" void kernel_launch(void* const* d_in, const int* in_sizes, int n_in,
                              void* d_out, int out_size) {
  (void)in_sizes; (void)n_in; (void)out_size;
  const float* x     = (const float*)d_in[0];
  const int*   seq   = (const int*)  d_in[1];
  const float* W_tp  = (const float*)d_in[2];
  const float* b_tp  = (const float*)d_in[3];
  const float* W_tc  = (const float*)d_in[4];
  const float* b_tc  = (const float*)d_in[5];
  const float* W_fij = (const float*)d_in[6];
  const float* w_root= (const float*)d_in[7];
  const float* r_emb = (const float*)d_in[8];
  const float* W_r   = (const float*)d_in[9];
  const float* b_r   = (const float*)d_in[10];
  const float* W_pc  = (const float*)d_in[11];
  const float* b_pc  = (const float*)d_in[12];
  float* out1 = (float*)d_out;
  float* out2 = out1 + (size_t)BT*SD;

  float *st,*se,*tp,*tc,*gg,*A,*cat,*cat2;
  cudaGetSymbolAddress((void**)&st,   g_st);
  cudaGetSymbolAddress((void**)&se,   g_se);
  cudaGetSymbolAddress((void**)&tp,   g_tp);
  cudaGetSymbolAddress((void**)&tc,   g_tc);
  cudaGetSymbolAddress((void**)&gg,   g_gg);
  cudaGetSymbolAddress((void**)&A,    g_A);
  cudaGetSymbolAddress((void**)&cat,  g_cat);
  cudaGetSymbolAddress((void**)&cat2, g_cat2);

  const int PANEL_SMEM  = TT*65*4;              // 133120
  const int UPDATE_SMEM = TT*65*4 + NB*132*4;   // 166912
  cudaFuncSetAttribute(panel_k,  cudaFuncAttributeMaxDynamicSharedMemorySize, PANEL_SMEM);
  cudaFuncSetAttribute(update_k, cudaFuncAttributeMaxDynamicSharedMemorySize, UPDATE_SMEM);

  const long long sTT = (long long)TT*TT, sTS = (long long)TT*SD,
                  sTH = (long long)TT*HD, sP = (long long)TT1*TT;
  const float* pij = out2 + TT;   // rows 1..512 of each (513,512) batch slab

  split_k<<<BT*HD/256, 256>>>(x);
  gemm_k<0><<<dim3(4,256,1),256>>>(st, SD, 0, W_tp, SD, 0, tp, SD, 0, SD, b_tp, 1, 0);
  gemm_k<0><<<dim3(4,256,1),256>>>(st, SD, 0, W_tc, SD, 0, tc, SD, 0, SD, b_tc, 1, 0);
  gemm_k<1><<<dim3(4,256,1),256>>>(tp, SD, 0, W_fij, SD, 0, gg, SD, 0, SD, 0, 0, 0);
  // batched f_ij with fused exp+mask -> writes A directly
  gemm_k<0><<<dim3(8,8,BB),256>>>(gg, SD, sTS, tc, SD, sTS, A, TT, sTT, SD, 0, 3, seq);
  root_k<<<BT*32/256, 256>>>(w_root, seq);
  colsum_k<<<BB, TT>>>();
  buildL_k<<<MT/256, 256>>>(seq);
  for (int kb = 0; kb < TT/NB; ++kb) {
    panel_k<<<BB, 1024, PANEL_SMEM>>>(kb*NB);
    update_k<<<dim3(4, BB), 1024, UPDATE_SMEM>>>(kb*NB);
  }
  gather_k<<<BB, 1024>>>();
  diag_k<<<BB, TT>>>(out2);
  pij_k<<<dim3(16,16,BB), dim3(32,32)>>>(out2);
  // parents: cat[:,0:256] = pij^T @ se   (tf32)
  tgemm_k<2><<<dim3(4,4,BB),256>>>(pij, TT, sP, se, SD, sTS, cat, HD, sTH, TT, 0, 0);
  addroot_k<<<MS/256, 256>>>(r_emb, out2);
  // children: cat[:,256:512] = pij @ se  (tf32)
  tgemm_k<1><<<dim3(4,4,BB),256>>>(pij, TT, sP, se, SD, sTS, cat + SD, HD, sTH, TT, 0, 0);
  // out = leaky(cat @ W_r^T + b_r)       (tf32)
  tgemm_k<0><<<dim3(4,128,1),256>>>(cat, HD, 0, W_r, HD, 0, cat2, HD, 0, HD, b_r, 2);
  // cp = pij @ out                        (tf32)
  tgemm_k<1><<<dim3(4,4,BB),256>>>(pij, TT, sP, cat2, HD, sTH, cat2 + SD, HD, sTH, TT, 0, 0);
  // out1 = leaky(cat2 @ W_pc^T + b_pc)    (tf32)
  tgemm_k<0><<<dim3(4,128,1),256>>>(cat2, HD, 0, W_pc, HD, 0, out1, SD, 0, HD, b_pc, 2);
}

// round 9
// speedup vs baseline: 1.2101x; 1.2101x over previous
#include <cuda_runtime.h>
#include <math.h>

#define BB 32
#define TT 512
#define TT1 513
#define SD 256
#define HD 512
#define BT (BB*TT)
#define MS (BT*SD)
#define MT (BT*TT)
#define NB 32

__device__ __align__(128) float g_st[MS], g_se[MS], g_tp[MS], g_tc[MS], g_gg[MS];
__device__ __align__(128) float g_A[MT], g_L[MT], g_Li[MT], g_cat[MT], g_cat2[MT];
__device__ __align__(128) float g_cs[BT], g_ar[BT], g_dg[BT];
__device__ __align__(128) int   g_piv[BT];

// ---------------- elementwise ----------------
__global__ void split_k(const float* __restrict__ x) {
  int idx = blockIdx.x*blockDim.x + threadIdx.x;
  int c = idx & 511; int bt = idx >> 9;
  const float* xp = x + (size_t)bt*HD;
  if (c < SD) g_se[(size_t)bt*SD + c] = xp[c + ((c >= 128) ? 128 : 0)];
  else { int cc = c - SD; g_st[(size_t)bt*SD + cc] = xp[cc + 128 + ((cc >= 128) ? 128 : 0)]; }
}

__global__ void root_k(const float* __restrict__ wr, const int* __restrict__ seq) {
  int g = blockIdx.x*blockDim.x + threadIdx.x;
  int w = g >> 5, lane = g & 31;
  if (w >= BT) return;
  const float* s = g_st + (size_t)w*SD;
  float acc = 0.f;
  for (int c = lane; c < SD; c += 32) acc += s[c]*wr[c];
  for (int o = 16; o > 0; o >>= 1) acc += __shfl_down_sync(0xffffffffu, acc, o);
  if (lane == 0) {
    int b = w >> 9, t = w & 511;
    g_ar[w] = (t < seq[b]) ? expf(acc) : 0.0f;
  }
}

__global__ void zcs_k() {
  g_cs[blockIdx.x*1024 + threadIdx.x] = 0.0f;
}

// partial column sums: grid (8, BB), each block sums 64 rows
__global__ void colsum_k() {
  int b = blockIdx.y, j = threadIdx.x;
  int i0 = blockIdx.x*64;
  const float* a = g_A + (size_t)b*TT*TT;
  float s = 0.f;
  #pragma unroll 8
  for (int i = i0; i < i0+64; ++i) s += a[(size_t)i*TT + j];
  atomicAdd(&g_cs[b*TT + j], s);
}

__global__ void buildL_k(const int* __restrict__ seq) {
  int idx = blockIdx.x*blockDim.x + threadIdx.x;
  int j = idx & 511, i = (idx >> 9) & 511, b = idx >> 18;
  float v;
  if (i == 0) v = g_ar[b*TT + j];
  else {
    v = -g_A[idx];
    if (i == j) v += g_cs[b*TT + j] + ((j >= seq[b]) ? 1.0f : 0.0f);
  }
  g_L[idx] = v;
}

// ---------------- blocked Gauss-Jordan inverse (NB=32, partial pivoting) ----------------
__global__ __launch_bounds__(1024) void panel_k(int k0) {
  extern __shared__ float panel[];  // 512 x 33
  __shared__ float colM[TT];
  __shared__ float redv[32]; __shared__ int redi[32];
  __shared__ float sPinv; __shared__ int sIr;
  __shared__ int spiv[NB];
  int b = blockIdx.x, tid = threadIdx.x;
  float* a = g_L + (size_t)b*TT*TT;
  for (int idx = tid; idx < TT*NB; idx += 1024) {
    int i = idx >> 5, c = idx & 31;
    panel[i*33+c] = a[(size_t)i*TT + k0 + c];
  }
  __syncthreads();
  for (int kk = 0; kk < NB; ++kk) {
    int k = k0 + kk;
    float v = -1.0f; int ix = tid;
    if (tid < TT && tid >= k) v = fabsf(panel[tid*33+kk]);
    for (int o = 16; o > 0; o >>= 1) {
      float v2 = __shfl_down_sync(0xffffffffu, v, o);
      int   i2 = __shfl_down_sync(0xffffffffu, ix, o);
      if (v2 > v) { v = v2; ix = i2; }
    }
    if ((tid & 31) == 0) { redv[tid>>5] = v; redi[tid>>5] = ix; }
    __syncthreads();
    if (tid == 0) {
      float bv = redv[0]; int bi = redi[0];
      for (int w = 1; w < 32; ++w) if (redv[w] > bv) { bv = redv[w]; bi = redi[w]; }
      sIr = bi; spiv[kk] = bi; g_piv[b*TT+k] = bi;
    }
    __syncthreads();
    int ir = sIr;
    if (ir != k && tid < NB) {
      float t = panel[k*33+tid]; panel[k*33+tid] = panel[ir*33+tid]; panel[ir*33+tid] = t;
    }
    __syncthreads();
    if (tid == 0) sPinv = 1.0f / panel[k*33+kk];
    __syncthreads();
    float pinv = sPinv;
    if (tid < NB) {
      float val = panel[k*33+tid];
      if (tid == kk) val = 1.0f;
      panel[k*33+tid] = val * pinv;
    } else if (tid >= 64 && tid < 64+TT) {
      colM[tid-64] = panel[(tid-64)*33+kk];
    }
    __syncthreads();
    for (int idx = tid; idx < TT*NB; idx += 1024) {
      int i = idx >> 5, c = idx & 31;
      if (i == k) continue;
      float m  = colM[i];
      float rk = panel[k*33+c];
      float cur = (c == kk) ? 0.0f : panel[i*33+c];
      panel[i*33+c] = cur - m*rk;
    }
    __syncthreads();
  }
  for (int s = 0; s < NB; ++s) {
    int k = k0 + s, ir = spiv[s];
    if (ir != k && tid < 128) {
      float4* rk = (float4*)(a + (size_t)k*TT);
      float4* rr = (float4*)(a + (size_t)ir*TT);
      float4 t = rk[tid]; rk[tid] = rr[tid]; rr[tid] = t;
    }
    __syncthreads();
  }
  for (int idx = tid; idx < TT*NB; idx += 1024) {
    int i = idx >> 5, c = idx & 31;
    a[(size_t)i*TT + k0 + c] = panel[i*33+c];
  }
}

__global__ __launch_bounds__(1024) void update_k(int k0) {
  extern __shared__ float sm[];
  float* Ps = sm;           // 512 x 33
  float* Rs = sm + TT*33;   // 32 x 132
  int b = blockIdx.y, tid = threadIdx.x;
  int jbase = blockIdx.x * 128;
  float* a = g_L + (size_t)b*TT*TT;
  for (int idx = tid; idx < TT*NB; idx += 1024) {
    int i = idx >> 5, c = idx & 31;
    Ps[i*33+c] = a[(size_t)i*TT + k0 + c];
  }
  for (int idx = tid; idx < NB*128; idx += 1024) {
    int k = idx >> 7, c = idx & 127;
    Rs[k*132+c] = a[(size_t)(k0+k)*TT + jbase + c];
  }
  __syncthreads();
  int tx = tid & 31, ty = tid >> 5;
  int j = jbase + tx*4;
  if (j >= k0 && j < k0 + NB) return;
  for (int r = 0; r < 4; ++r) {
    int i0 = r*128 + ty*4;
    float acc[4][4] = {};
#pragma unroll 8
    for (int k = 0; k < NB; ++k) {
      float4 rv = *(const float4*)(Rs + k*132 + tx*4);
      float p0 = Ps[(i0+0)*33+k], p1 = Ps[(i0+1)*33+k];
      float p2 = Ps[(i0+2)*33+k], p3 = Ps[(i0+3)*33+k];
      acc[0][0]+=p0*rv.x; acc[0][1]+=p0*rv.y; acc[0][2]+=p0*rv.z; acc[0][3]+=p0*rv.w;
      acc[1][0]+=p1*rv.x; acc[1][1]+=p1*rv.y; acc[1][2]+=p1*rv.z; acc[1][3]+=p1*rv.w;
      acc[2][0]+=p2*rv.x; acc[2][1]+=p2*rv.y; acc[2][2]+=p2*rv.z; acc[2][3]+=p2*rv.w;
      acc[3][0]+=p3*rv.x; acc[3][1]+=p3*rv.y; acc[3][2]+=p3*rv.z; acc[3][3]+=p3*rv.w;
    }
#pragma unroll
    for (int q = 0; q < 4; ++q) {
      int i = i0 + q;
      float4 res;
      if (i >= k0 && i < k0 + NB) res = make_float4(0.f,0.f,0.f,0.f);
      else res = *(const float4*)(a + (size_t)i*TT + j);
      res.x += acc[q][0]; res.y += acc[q][1]; res.z += acc[q][2]; res.w += acc[q][3];
      *(float4*)(a + (size_t)i*TT + j) = res;
    }
  }
}

// grid (4, BB): each block handles a 128-row slice; arr recomputed per block
__global__ __launch_bounds__(1024) void gather_k() {
  __shared__ int arr[TT];
  int b = blockIdx.y, tid = threadIdx.x;
  if (tid == 0) {
    for (int j = 0; j < TT; ++j) arr[j] = j;
    for (int l = TT-1; l >= 0; --l) {
      int p = g_piv[b*TT + l];
      if (p != l) { int t = arr[l]; arr[l] = arr[p]; arr[p] = t; }
    }
  }
  __syncthreads();
  const float* a = g_L + (size_t)b*TT*TT;
  float* o = g_Li + (size_t)b*TT*TT;
  int base = blockIdx.x * 128 * TT;
  for (int idx = tid; idx < 128*TT; idx += 1024) {
    int i = idx >> 9, j = idx & 511;
    o[base + idx] = a[(size_t)(blockIdx.x*128 + i)*TT + arr[j]];
  }
}

__global__ void diag_k(float* __restrict__ out2) {
  int b = blockIdx.x, j = threadIdx.x;
  const float* L = g_Li + (size_t)b*TT*TT;
  g_dg[b*TT + j] = L[(size_t)j*TT + j];
  out2[(size_t)b*TT1*TT + j] = g_ar[b*TT + j] * L[(size_t)j*TT];
}

__global__ __launch_bounds__(1024) void pij_k(float* __restrict__ out2) {
  __shared__ float Ts[32][33];
  int b = blockIdx.z;
  int i0 = blockIdx.y*32, j0 = blockIdx.x*32;
  int tx = threadIdx.x, ty = threadIdx.y;
  const float* L = g_Li + (size_t)b*TT*TT;
  Ts[ty][tx] = L[(size_t)(j0+ty)*TT + i0 + tx];
  __syncthreads();
  int i = i0 + ty, j = j0 + tx;
  float av  = g_A[(size_t)b*TT*TT + (size_t)i*TT + j];
  float dj  = (j > 0) ? g_dg[b*TT + j] : 0.0f;
  float lji = (i > 0) ? Ts[tx][ty] : 0.0f;
  out2[(size_t)b*TT1*TT + (size_t)(i+1)*TT + j] = av * (dj - lji);
}

__global__ void addroot_k(const float* __restrict__ re, const float* __restrict__ out2) {
  int idx = blockIdx.x*blockDim.x + threadIdx.x;
  int c = idx & 255, bi = idx >> 8;
  int b = bi >> 9, i = bi & 511;
  float pr = out2[(size_t)b*TT1*TT + i];
  g_cat[(size_t)bi*HD + c] += pr * re[c];
}

// ---------------- SIMT tiled GEMM (fp32-exact path) ----------------
// MODE 0: C = A(MxK)*B(NxK)^T ; MODE 1: C = A(MxK)*B(KxN)
// act: 0 none, 1 tanh, 3 exp+tree-mask
#define BKD 16
#define PADW 68
template<int MODE>
__global__ __launch_bounds__(256)
void gemm_k(const float* __restrict__ A, int lda, long long sA,
            const float* __restrict__ B, int ldb, long long sB,
            float* __restrict__ C, int ldc, long long sC,
            int K, const float* __restrict__ bias, int act, const int* __restrict__ seq)
{
  __shared__ __align__(16) float As[BKD*PADW];
  __shared__ __align__(16) float Bs[BKD*PADW];
  const int tid = threadIdx.x;
  const int tx = tid & 15, ty = tid >> 4;
  const int m0 = blockIdx.y*64, n0 = blockIdx.x*64;
  const float* Ab = A + (size_t)blockIdx.z*sA;
  const float* Bb = B + (size_t)blockIdx.z*sB;
  float* Cb = C + (size_t)blockIdx.z*sC;
  const int r4 = tid >> 2, k4 = (tid & 3)*4;
  const int k16 = tid >> 4, c16 = (tid & 15)*4;
  float acc[4][4] = {};
  for (int k0 = 0; k0 < K; k0 += BKD) {
    float4 aL = *(const float4*)(Ab + (size_t)(m0+r4)*lda + k0 + k4);
    float4 bL;
    if (MODE == 0) bL = *(const float4*)(Bb + (size_t)(n0+r4)*ldb + k0 + k4);
    else           bL = *(const float4*)(Bb + (size_t)(k0+k16)*ldb + n0 + c16);
    __syncthreads();
    As[(k4+0)*PADW + r4] = aL.x; As[(k4+1)*PADW + r4] = aL.y;
    As[(k4+2)*PADW + r4] = aL.z; As[(k4+3)*PADW + r4] = aL.w;
    if (MODE == 0) {
      Bs[(k4+0)*PADW + r4] = bL.x; Bs[(k4+1)*PADW + r4] = bL.y;
      Bs[(k4+2)*PADW + r4] = bL.z; Bs[(k4+3)*PADW + r4] = bL.w;
    } else *(float4*)(Bs + k16*PADW + c16) = bL;
    __syncthreads();
#pragma unroll
    for (int kk = 0; kk < BKD; ++kk) {
      float4 av = *(const float4*)(As + kk*PADW + ty*4);
      float4 bv = *(const float4*)(Bs + kk*PADW + tx*4);
      acc[0][0] += av.x*bv.x; acc[0][1] += av.x*bv.y; acc[0][2] += av.x*bv.z; acc[0][3] += av.x*bv.w;
      acc[1][0] += av.y*bv.x; acc[1][1] += av.y*bv.y; acc[1][2] += av.y*bv.z; acc[1][3] += av.y*bv.w;
      acc[2][0] += av.z*bv.x; acc[2][1] += av.z*bv.y; acc[2][2] += av.z*bv.z; acc[2][3] += av.z*bv.w;
      acc[3][0] += av.w*bv.x; acc[3][1] += av.w*bv.y; acc[3][2] += av.w*bv.z; acc[3][3] += av.w*bv.w;
    }
  }
  float4 bb = make_float4(0.f,0.f,0.f,0.f);
  if (bias) { const float* bp = bias + n0 + tx*4; bb = make_float4(bp[0],bp[1],bp[2],bp[3]); }
  int len = (act == 3) ? seq[blockIdx.z] : 0;
#pragma unroll
  for (int i = 0; i < 4; ++i) {
    float4 v = make_float4(acc[i][0]+bb.x, acc[i][1]+bb.y, acc[i][2]+bb.z, acc[i][3]+bb.w);
    if (act == 1) { v.x=tanhf(v.x); v.y=tanhf(v.y); v.z=tanhf(v.z); v.w=tanhf(v.w); }
    else if (act == 3) {
      int gi = m0 + ty*4 + i, gj = n0 + tx*4;
      float* pv = (float*)&v;
#pragma unroll
      for (int q = 0; q < 4; ++q) {
        int j = gj + q;
        pv[q] = (gi != j && gi < len && j < len) ? expf(pv[q]) : 0.0f;
      }
    }
    *(float4*)(Cb + (size_t)(m0+ty*4+i)*ldc + n0 + tx*4) = v;
  }
}

// ---------------- tf32 tensor-core GEMM (out1 path) ----------------
#define TFA 136
#define TFB 72
__device__ __forceinline__ float f2tf(float f) {
  unsigned u; asm("cvt.rna.tf32.f32 %0, %1;" : "=r"(u) : "f"(f));
  return __uint_as_float(u);
}
template<int MODE>
__global__ __launch_bounds__(256)
void tgemm_k(const float* __restrict__ A, int lda, long long sA,
             const float* __restrict__ B, int ldb, long long sB,
             float* __restrict__ C, int ldc, long long sC,
             int K, const float* __restrict__ bias, int act)
{
  __shared__ __align__(16) float As[16*TFA];
  __shared__ __align__(16) float Bs[16*TFB];
  int tid = threadIdx.x;
  int m0 = blockIdx.y*128, n0 = blockIdx.x*64;
  const float* Ab = A + (size_t)blockIdx.z*sA;
  const float* Bb = B + (size_t)blockIdx.z*sB;
  float* Cb = C + (size_t)blockIdx.z*sC;
  int warp = tid>>5, lane = tid&31;
  int wm = (warp&3)*32, wn = (warp>>2)*32;
  int g = lane>>2, la3 = lane&3;
  float acc[2][4][4];
#pragma unroll
  for(int a=0;a<2;a++)
#pragma unroll
    for(int b=0;b<4;b++)
#pragma unroll
      for(int c=0;c<4;c++) acc[a][b][c]=0.f;

  for (int k0 = 0; k0 < K; k0 += 16) {
    __syncthreads();
#pragma unroll
    for (int q = 0; q < 2; ++q) {
      int idx = tid + q*256;
      if (MODE == 2) {
        int kr = idx >> 5, c4 = (idx & 31)*4;
        float4 v = *(const float4*)(Ab + (size_t)(k0+kr)*lda + m0 + c4);
        v.x = f2tf(v.x); v.y = f2tf(v.y); v.z = f2tf(v.z); v.w = f2tf(v.w);
        *(float4*)(As + kr*TFA + c4) = v;
      } else {
        int r = idx >> 2, c4 = (idx & 3)*4;
        float4 v = *(const float4*)(Ab + (size_t)(m0+r)*lda + k0 + c4);
        As[(c4+0)*TFA + r] = f2tf(v.x); As[(c4+1)*TFA + r] = f2tf(v.y);
        As[(c4+2)*TFA + r] = f2tf(v.z); As[(c4+3)*TFA + r] = f2tf(v.w);
      }
    }
    {
      int idx = tid;
      if (MODE == 0) {
        int r = idx >> 2, c4 = (idx & 3)*4;
        float4 v = *(const float4*)(Bb + (size_t)(n0+r)*ldb + k0 + c4);
        Bs[(c4+0)*TFB + r] = f2tf(v.x); Bs[(c4+1)*TFB + r] = f2tf(v.y);
        Bs[(c4+2)*TFB + r] = f2tf(v.z); Bs[(c4+3)*TFB + r] = f2tf(v.w);
      } else {
        int kr = idx >> 4, c4 = (idx & 15)*4;
        float4 v = *(const float4*)(Bb + (size_t)(k0+kr)*ldb + n0 + c4);
        v.x = f2tf(v.x); v.y = f2tf(v.y); v.z = f2tf(v.z); v.w = f2tf(v.w);
        *(float4*)(Bs + kr*TFB + c4) = v;
      }
    }
    __syncthreads();
#pragma unroll
    for (int ks = 0; ks < 2; ++ks) {
      int kb = ks*8;
      unsigned af[2][4];
#pragma unroll
      for (int mt = 0; mt < 2; ++mt) {
        const float* ap = As + (kb + la3)*TFA + wm + mt*16 + g;
        af[mt][0] = __float_as_uint(ap[0]);
        af[mt][1] = __float_as_uint(ap[8]);
        af[mt][2] = __float_as_uint(ap[4*TFA]);
        af[mt][3] = __float_as_uint(ap[4*TFA + 8]);
      }
#pragma unroll
      for (int nt = 0; nt < 4; ++nt) {
        const float* bp = Bs + (kb + la3)*TFB + wn + nt*8 + g;
        unsigned b0 = __float_as_uint(bp[0]);
        unsigned b1 = __float_as_uint(bp[4*TFB]);
#pragma unroll
        for (int mt = 0; mt < 2; ++mt) {
          asm volatile("mma.sync.aligned.m16n8k8.row.col.f32.tf32.tf32.f32 "
            "{%0,%1,%2,%3}, {%4,%5,%6,%7}, {%8,%9}, {%0,%1,%2,%3};"
            : "+f"(acc[mt][nt][0]), "+f"(acc[mt][nt][1]),
              "+f"(acc[mt][nt][2]), "+f"(acc[mt][nt][3])
            : "r"(af[mt][0]), "r"(af[mt][1]), "r"(af[mt][2]), "r"(af[mt][3]),
              "r"(b0), "r"(b1));
        }
      }
    }
  }
#pragma unroll
  for (int mt = 0; mt < 2; ++mt) {
    int mrow = m0 + wm + mt*16 + g;
#pragma unroll
    for (int nt = 0; nt < 4; ++nt) {
      int ncol = n0 + wn + nt*8 + la3*2;
      float b0v = 0.f, b1v = 0.f;
      if (bias) { b0v = bias[ncol]; b1v = bias[ncol+1]; }
      float v0 = acc[mt][nt][0] + b0v, v1 = acc[mt][nt][1] + b1v;
      float v2 = acc[mt][nt][2] + b0v, v3 = acc[mt][nt][3] + b1v;
      if (act == 2) {
        v0 = v0>=0.f?v0:0.01f*v0; v1 = v1>=0.f?v1:0.01f*v1;
        v2 = v2>=0.f?v2:0.01f*v2; v3 = v3>=0.f?v3:0.01f*v3;
      }
      *(float2*)(Cb + (size_t)mrow*ldc + ncol) = make_float2(v0, v1);
      *(float2*)(Cb + (size_t)(mrow+8)*ldc + ncol) = make_float2(v2, v3);
    }
  }
}

// ---------------- launch ----------------
extern "C" void kernel_launch(void* const* d_in, const int* in_sizes, int n_in,
                              void* d_out, int out_size) {
  (void)in_sizes; (void)n_in; (void)out_size;
  const float* x     = (const float*)d_in[0];
  const int*   seq   = (const int*)  d_in[1];
  const float* W_tp  = (const float*)d_in[2];
  const float* b_tp  = (const float*)d_in[3];
  const float* W_tc  = (const float*)d_in[4];
  const float* b_tc  = (const float*)d_in[5];
  const float* W_fij = (const float*)d_in[6];
  const float* w_root= (const float*)d_in[7];
  const float* r_emb = (const float*)d_in[8];
  const float* W_r   = (const float*)d_in[9];
  const float* b_r   = (const float*)d_in[10];
  const float* W_pc  = (const float*)d_in[11];
  const float* b_pc  = (const float*)d_in[12];
  float* out1 = (float*)d_out;
  float* out2 = out1 + (size_t)BT*SD;

  float *st,*se,*tp,*tc,*gg,*A,*cat,*cat2;
  cudaGetSymbolAddress((void**)&st,   g_st);
  cudaGetSymbolAddress((void**)&se,   g_se);
  cudaGetSymbolAddress((void**)&tp,   g_tp);
  cudaGetSymbolAddress((void**)&tc,   g_tc);
  cudaGetSymbolAddress((void**)&gg,   g_gg);
  cudaGetSymbolAddress((void**)&A,    g_A);
  cudaGetSymbolAddress((void**)&cat,  g_cat);
  cudaGetSymbolAddress((void**)&cat2, g_cat2);

  const int PANEL_SMEM  = TT*33*4;              // 67584
  const int UPDATE_SMEM = TT*33*4 + NB*132*4;   // 84480
  cudaFuncSetAttribute(panel_k,  cudaFuncAttributeMaxDynamicSharedMemorySize, PANEL_SMEM);
  cudaFuncSetAttribute(update_k, cudaFuncAttributeMaxDynamicSharedMemorySize, UPDATE_SMEM);

  const long long sTT = (long long)TT*TT, sTS = (long long)TT*SD,
                  sTH = (long long)TT*HD, sP = (long long)TT1*TT;
  const float* pij = out2 + TT;   // rows 1..512 of each (513,512) batch slab

  split_k<<<BT*HD/256, 256>>>(x);
  gemm_k<0><<<dim3(4,256,1),256>>>(st, SD, 0, W_tp, SD, 0, tp, SD, 0, SD, b_tp, 1, 0);
  gemm_k<0><<<dim3(4,256,1),256>>>(st, SD, 0, W_tc, SD, 0, tc, SD, 0, SD, b_tc, 1, 0);
  gemm_k<1><<<dim3(4,256,1),256>>>(tp, SD, 0, W_fij, SD, 0, gg, SD, 0, SD, 0, 0, 0);
  // batched f_ij with fused exp+mask -> writes A directly
  gemm_k<0><<<dim3(8,8,BB),256>>>(gg, SD, sTS, tc, SD, sTS, A, TT, sTT, SD, 0, 3, seq);
  root_k<<<BT*32/256, 256>>>(w_root, seq);
  zcs_k<<<BT/1024, 1024>>>();
  colsum_k<<<dim3(8,BB), 512>>>();
  buildL_k<<<MT/256, 256>>>(seq);
  for (int kb = 0; kb < TT/NB; ++kb) {
    panel_k<<<BB, 1024, PANEL_SMEM>>>(kb*NB);
    update_k<<<dim3(4, BB), 1024, UPDATE_SMEM>>>(kb*NB);
  }
  gather_k<<<dim3(4, BB), 1024>>>();
  diag_k<<<BB, TT>>>(out2);
  pij_k<<<dim3(16,16,BB), dim3(32,32)>>>(out2);
  // parents: cat[:,0:256] = pij^T @ se   (tf32)
  tgemm_k<2><<<dim3(4,4,BB),256>>>(pij, TT, sP, se, SD, sTS, cat, HD, sTH, TT, 0, 0);
  addroot_k<<<MS/256, 256>>>(r_emb, out2);
  // children: cat[:,256:512] = pij @ se  (tf32)
  tgemm_k<1><<<dim3(4,4,BB),256>>>(pij, TT, sP, se, SD, sTS, cat + SD, HD, sTH, TT, 0, 0);
  // out = leaky(cat @ W_r^T + b_r)       (tf32)
  tgemm_k<0><<<dim3(4,128,1),256>>>(cat, HD, 0, W_r, HD, 0, cat2, HD, 0, HD, b_r, 2);
  // cp = pij @ out                        (tf32)
  tgemm_k<1><<<dim3(4,4,BB),256>>>(pij, TT, sP, cat2, HD, sTH, cat2 + SD, HD, sTH, TT, 0, 0);
  // out1 = leaky(cat2 @ W_pc^T + b_pc)    (tf32)
  tgemm_k<0><<<dim3(4,128,1),256>>>(cat2, HD, 0, W_pc, HD, 0, out1, SD, 0, HD, b_pc, 2);
}

// round 10
// speedup vs baseline: 1.3419x; 1.1089x over previous
#include <cuda_runtime.h>
#include <math.h>

#define BB 32
#define TT 512
#define TT1 513
#define SD 256
#define HD 512
#define BT (BB*TT)
#define MS (BT*SD)
#define MT (BT*TT)
#define NB 32

__device__ __align__(128) float g_st[MS], g_se[MS], g_tp[MS], g_tc[MS], g_gg[MS];
__device__ __align__(128) float g_A[MT], g_L[MT], g_Li[MT], g_cat[MT], g_cat2[MT];
__device__ __align__(128) float g_cs[BT], g_ar[BT], g_dg[BT];
__device__ __align__(128) int   g_piv[BT];
__device__ __align__(128) int   g_srcrow[BT];

// ---------------- elementwise ----------------
__global__ void split_k(const float* __restrict__ x) {
  int idx = blockIdx.x*blockDim.x + threadIdx.x;
  int c = idx & 511; int bt = idx >> 9;
  const float* xp = x + (size_t)bt*HD;
  if (c < SD) g_se[(size_t)bt*SD + c] = xp[c + ((c >= 128) ? 128 : 0)];
  else { int cc = c - SD; g_st[(size_t)bt*SD + cc] = xp[cc + 128 + ((cc >= 128) ? 128 : 0)]; }
}

__global__ void root_k(const float* __restrict__ wr, const int* __restrict__ seq) {
  int g = blockIdx.x*blockDim.x + threadIdx.x;
  int w = g >> 5, lane = g & 31;
  if (w >= BT) return;
  const float* s = g_st + (size_t)w*SD;
  float acc = 0.f;
  for (int c = lane; c < SD; c += 32) acc += s[c]*wr[c];
  for (int o = 16; o > 0; o >>= 1) acc += __shfl_down_sync(0xffffffffu, acc, o);
  if (lane == 0) {
    int b = w >> 9, t = w & 511;
    g_ar[w] = (t < seq[b]) ? expf(acc) : 0.0f;
  }
}

__global__ void zcs_k() {
  g_cs[blockIdx.x*1024 + threadIdx.x] = 0.0f;
}

__global__ void colsum_k() {
  int b = blockIdx.y, j = threadIdx.x;
  int i0 = blockIdx.x*64;
  const float* a = g_A + (size_t)b*TT*TT;
  float s = 0.f;
  #pragma unroll 8
  for (int i = i0; i < i0+64; ++i) s += a[(size_t)i*TT + j];
  atomicAdd(&g_cs[b*TT + j], s);
}

__global__ void buildL_k(const int* __restrict__ seq) {
  int idx = blockIdx.x*blockDim.x + threadIdx.x;
  int j = idx & 511, i = (idx >> 9) & 511, b = idx >> 18;
  float v;
  if (i == 0) v = g_ar[b*TT + j];
  else {
    v = -g_A[idx];
    if (i == j) v += g_cs[b*TT + j] + ((j >= seq[b]) ? 1.0f : 0.0f);
  }
  g_L[idx] = v;
}

// ---------------- blocked Gauss-Jordan inverse (NB=32, partial pivoting) ----------------
// panel_k: factor block columns in smem (pivot sequence identical to unblocked GJ),
// record the row permutation (no gmem swaps), write finalized panel to DST.
__global__ __launch_bounds__(1024) void panel_k(const float* __restrict__ srcM,
                                                float* __restrict__ dstM, int k0) {
  extern __shared__ float panel[];  // 512 x 33
  __shared__ float colM[TT];
  __shared__ int rowmap[TT];
  __shared__ float redv[32]; __shared__ int redi[32];
  __shared__ int sIr;
  int b = blockIdx.x, tid = threadIdx.x;
  const float* src = srcM + (size_t)b*TT*TT;
  float* dst = dstM + (size_t)b*TT*TT;
  for (int idx = tid; idx < TT*NB; idx += 1024) {
    int i = idx >> 5, c = idx & 31;
    panel[i*33+c] = src[(size_t)i*TT + k0 + c];
  }
  if (tid < TT) rowmap[tid] = tid;
  __syncthreads();
  for (int kk = 0; kk < NB; ++kk) {
    int k = k0 + kk;
    // pivot search over smem column kk, rows >= k
    float v = -1.0f; int ix = tid;
    if (tid < TT && tid >= k) v = fabsf(panel[tid*33+kk]);
    for (int o = 16; o > 0; o >>= 1) {
      float v2 = __shfl_down_sync(0xffffffffu, v, o);
      int   i2 = __shfl_down_sync(0xffffffffu, ix, o);
      if (v2 > v) { v = v2; ix = i2; }
    }
    if ((tid & 31) == 0) { redv[tid>>5] = v; redi[tid>>5] = ix; }
    __syncthreads();
    if (tid < 32) {
      float bv = redv[tid]; int bi = redi[tid];
      for (int o = 16; o > 0; o >>= 1) {
        float v2 = __shfl_down_sync(0xffffffffu, bv, o);
        int   i2 = __shfl_down_sync(0xffffffffu, bi, o);
        if (v2 > bv) { bv = v2; bi = i2; }
      }
      if (tid == 0) { sIr = bi; g_piv[b*TT+k] = bi; }
    }
    __syncthreads();
    int ir = sIr;
    if (tid < NB) {
      if (ir != k) {
        float t = panel[k*33+tid]; panel[k*33+tid] = panel[ir*33+tid]; panel[ir*33+tid] = t;
      }
      if (tid == 0 && ir != k) { int t = rowmap[k]; rowmap[k] = rowmap[ir]; rowmap[ir] = t; }
    }
    __syncthreads();
    // scale row k (warp 0) + stage multiplier column (other threads)
    if (tid < NB) {
      float pv  = panel[k*33+kk];
      float val = panel[k*33+tid];
      __syncwarp();
      float pinv = 1.0f / pv;
      if (tid == kk) val = 1.0f;
      panel[k*33+tid] = val * pinv;
    } else if (tid >= 64 && tid < 64+TT) {
      colM[tid-64] = panel[(tid-64)*33+kk];   // colM[k] unused (i==k skipped)
    }
    __syncthreads();
    // rank-1 update (reads scaled row k in place; per-thread column is fixed)
    {
      int c = tid & 31;
      float rk = panel[k*33+c];
      for (int idx = tid; idx < TT*NB; idx += 1024) {
        int i = idx >> 5;
        if (i == k) continue;
        float m = colM[i];
        float cur = (c == kk) ? 0.0f : panel[i*33+c];
        panel[i*33+c] = cur - m*rk;
      }
    }
    __syncthreads();
  }
  if (tid < TT) g_srcrow[b*TT + tid] = rowmap[tid];
  for (int idx = tid; idx < TT*NB; idx += 1024) {
    int i = idx >> 5, c = idx & 31;
    dst[(size_t)i*TT + k0 + c] = panel[i*33+c];
  }
}

// update_k: DST[i][j] = [i not in blk]*SRC[sigma(i)][j] + P[i][:].R[:][j], j outside blk.
// P from DST block cols (written by panel_k), R = SRC[sigma(k0+k)] rows.
__global__ __launch_bounds__(1024) void update_k(const float* __restrict__ srcM,
                                                 float* __restrict__ dstM, int k0) {
  extern __shared__ float sm[];
  float* Ps = sm;           // 512 x 33
  float* Rs = sm + TT*33;   // 32 x 132
  __shared__ int smap[TT];
  int b = blockIdx.y, tid = threadIdx.x;
  int jbase = blockIdx.x * 128;
  const float* src = srcM + (size_t)b*TT*TT;
  float* dst = dstM + (size_t)b*TT*TT;
  if (tid < TT) smap[tid] = g_srcrow[b*TT + tid];
  __syncthreads();
  for (int idx = tid; idx < TT*NB; idx += 1024) {
    int i = idx >> 5, c = idx & 31;
    Ps[i*33+c] = dst[(size_t)i*TT + k0 + c];
  }
  for (int idx = tid; idx < NB*128; idx += 1024) {
    int k = idx >> 7, c = idx & 127;
    Rs[k*132+c] = src[(size_t)smap[k0+k]*TT + jbase + c];
  }
  __syncthreads();
  int tx = tid & 31, ty = tid >> 5;
  int j = jbase + tx*4;
  if (j >= k0 && j < k0 + NB) return;   // block cols written by panel_k
  for (int r = 0; r < 4; ++r) {
    int i0 = r*128 + ty*4;
    float acc[4][4] = {};
#pragma unroll 8
    for (int k = 0; k < NB; ++k) {
      float4 rv = *(const float4*)(Rs + k*132 + tx*4);
      float p0 = Ps[(i0+0)*33+k], p1 = Ps[(i0+1)*33+k];
      float p2 = Ps[(i0+2)*33+k], p3 = Ps[(i0+3)*33+k];
      acc[0][0]+=p0*rv.x; acc[0][1]+=p0*rv.y; acc[0][2]+=p0*rv.z; acc[0][3]+=p0*rv.w;
      acc[1][0]+=p1*rv.x; acc[1][1]+=p1*rv.y; acc[1][2]+=p1*rv.z; acc[1][3]+=p1*rv.w;
      acc[2][0]+=p2*rv.x; acc[2][1]+=p2*rv.y; acc[2][2]+=p2*rv.z; acc[2][3]+=p2*rv.w;
      acc[3][0]+=p3*rv.x; acc[3][1]+=p3*rv.y; acc[3][2]+=p3*rv.z; acc[3][3]+=p3*rv.w;
    }
#pragma unroll
    for (int q = 0; q < 4; ++q) {
      int i = i0 + q;
      float4 res;
      if (i >= k0 && i < k0 + NB) res = make_float4(0.f,0.f,0.f,0.f);
      else res = *(const float4*)(src + (size_t)smap[i]*TT + j);
      res.x += acc[q][0]; res.y += acc[q][1]; res.z += acc[q][2]; res.w += acc[q][3];
      *(float4*)(dst + (size_t)i*TT + j) = res;
    }
  }
}

// grid (4, BB): each block handles a 128-row slice; arr recomputed per block
__global__ __launch_bounds__(1024) void gather_k() {
  __shared__ int arr[TT];
  int b = blockIdx.y, tid = threadIdx.x;
  if (tid == 0) {
    for (int j = 0; j < TT; ++j) arr[j] = j;
    for (int l = TT-1; l >= 0; --l) {
      int p = g_piv[b*TT + l];
      if (p != l) { int t = arr[l]; arr[l] = arr[p]; arr[p] = t; }
    }
  }
  __syncthreads();
  const float* a = g_L + (size_t)b*TT*TT;
  float* o = g_Li + (size_t)b*TT*TT;
  int base = blockIdx.x * 128 * TT;
  for (int idx = tid; idx < 128*TT; idx += 1024) {
    int i = idx >> 9, j = idx & 511;
    o[base + idx] = a[(size_t)(blockIdx.x*128 + i)*TT + arr[j]];
  }
}

__global__ void diag_k(float* __restrict__ out2) {
  int b = blockIdx.x, j = threadIdx.x;
  const float* L = g_Li + (size_t)b*TT*TT;
  g_dg[b*TT + j] = L[(size_t)j*TT + j];
  out2[(size_t)b*TT1*TT + j] = g_ar[b*TT + j] * L[(size_t)j*TT];
}

__global__ __launch_bounds__(1024) void pij_k(float* __restrict__ out2) {
  __shared__ float Ts[32][33];
  int b = blockIdx.z;
  int i0 = blockIdx.y*32, j0 = blockIdx.x*32;
  int tx = threadIdx.x, ty = threadIdx.y;
  const float* L = g_Li + (size_t)b*TT*TT;
  Ts[ty][tx] = L[(size_t)(j0+ty)*TT + i0 + tx];
  __syncthreads();
  int i = i0 + ty, j = j0 + tx;
  float av  = g_A[(size_t)b*TT*TT + (size_t)i*TT + j];
  float dj  = (j > 0) ? g_dg[b*TT + j] : 0.0f;
  float lji = (i > 0) ? Ts[tx][ty] : 0.0f;
  out2[(size_t)b*TT1*TT + (size_t)(i+1)*TT + j] = av * (dj - lji);
}

__global__ void addroot_k(const float* __restrict__ re, const float* __restrict__ out2) {
  int idx = blockIdx.x*blockDim.x + threadIdx.x;
  int c = idx & 255, bi = idx >> 8;
  int b = bi >> 9, i = bi & 511;
  float pr = out2[(size_t)b*TT1*TT + i];
  g_cat[(size_t)bi*HD + c] += pr * re[c];
}

// ---------------- SIMT tiled GEMM (fp32-exact path) ----------------
#define BKD 16
#define PADW 68
template<int MODE>
__global__ __launch_bounds__(256)
void gemm_k(const float* __restrict__ A, int lda, long long sA,
            const float* __restrict__ B, int ldb, long long sB,
            float* __restrict__ C, int ldc, long long sC,
            int K, const float* __restrict__ bias, int act, const int* __restrict__ seq)
{
  __shared__ __align__(16) float As[BKD*PADW];
  __shared__ __align__(16) float Bs[BKD*PADW];
  const int tid = threadIdx.x;
  const int tx = tid & 15, ty = tid >> 4;
  const int m0 = blockIdx.y*64, n0 = blockIdx.x*64;
  const float* Ab = A + (size_t)blockIdx.z*sA;
  const float* Bb = B + (size_t)blockIdx.z*sB;
  float* Cb = C + (size_t)blockIdx.z*sC;
  const int r4 = tid >> 2, k4 = (tid & 3)*4;
  const int k16 = tid >> 4, c16 = (tid & 15)*4;
  float acc[4][4] = {};
  for (int k0 = 0; k0 < K; k0 += BKD) {
    float4 aL = *(const float4*)(Ab + (size_t)(m0+r4)*lda + k0 + k4);
    float4 bL;
    if (MODE == 0) bL = *(const float4*)(Bb + (size_t)(n0+r4)*ldb + k0 + k4);
    else           bL = *(const float4*)(Bb + (size_t)(k0+k16)*ldb + n0 + c16);
    __syncthreads();
    As[(k4+0)*PADW + r4] = aL.x; As[(k4+1)*PADW + r4] = aL.y;
    As[(k4+2)*PADW + r4] = aL.z; As[(k4+3)*PADW + r4] = aL.w;
    if (MODE == 0) {
      Bs[(k4+0)*PADW + r4] = bL.x; Bs[(k4+1)*PADW + r4] = bL.y;
      Bs[(k4+2)*PADW + r4] = bL.z; Bs[(k4+3)*PADW + r4] = bL.w;
    } else *(float4*)(Bs + k16*PADW + c16) = bL;
    __syncthreads();
#pragma unroll
    for (int kk = 0; kk < BKD; ++kk) {
      float4 av = *(const float4*)(As + kk*PADW + ty*4);
      float4 bv = *(const float4*)(Bs + kk*PADW + tx*4);
      acc[0][0] += av.x*bv.x; acc[0][1] += av.x*bv.y; acc[0][2] += av.x*bv.z; acc[0][3] += av.x*bv.w;
      acc[1][0] += av.y*bv.x; acc[1][1] += av.y*bv.y; acc[1][2] += av.y*bv.z; acc[1][3] += av.y*bv.w;
      acc[2][0] += av.z*bv.x; acc[2][1] += av.z*bv.y; acc[2][2] += av.z*bv.z; acc[2][3] += av.z*bv.w;
      acc[3][0] += av.w*bv.x; acc[3][1] += av.w*bv.y; acc[3][2] += av.w*bv.z; acc[3][3] += av.w*bv.w;
    }
  }
  float4 bb = make_float4(0.f,0.f,0.f,0.f);
  if (bias) { const float* bp = bias + n0 + tx*4; bb = make_float4(bp[0],bp[1],bp[2],bp[3]); }
  int len = (act == 3) ? seq[blockIdx.z] : 0;
#pragma unroll
  for (int i = 0; i < 4; ++i) {
    float4 v = make_float4(acc[i][0]+bb.x, acc[i][1]+bb.y, acc[i][2]+bb.z, acc[i][3]+bb.w);
    if (act == 1) { v.x=tanhf(v.x); v.y=tanhf(v.y); v.z=tanhf(v.z); v.w=tanhf(v.w); }
    else if (act == 3) {
      int gi = m0 + ty*4 + i, gj = n0 + tx*4;
      float* pv = (float*)&v;
#pragma unroll
      for (int q = 0; q < 4; ++q) {
        int j = gj + q;
        pv[q] = (gi != j && gi < len && j < len) ? expf(pv[q]) : 0.0f;
      }
    }
    *(float4*)(Cb + (size_t)(m0+ty*4+i)*ldc + n0 + tx*4) = v;
  }
}

// ---------------- tf32 tensor-core GEMM (out1 path) ----------------
#define TFA 136
#define TFB 72
__device__ __forceinline__ float f2tf(float f) {
  unsigned u; asm("cvt.rna.tf32.f32 %0, %1;" : "=r"(u) : "f"(f));
  return __uint_as_float(u);
}
template<int MODE>
__global__ __launch_bounds__(256)
void tgemm_k(const float* __restrict__ A, int lda, long long sA,
             const float* __restrict__ B, int ldb, long long sB,
             float* __restrict__ C, int ldc, long long sC,
             int K, const float* __restrict__ bias, int act)
{
  __shared__ __align__(16) float As[16*TFA];
  __shared__ __align__(16) float Bs[16*TFB];
  int tid = threadIdx.x;
  int m0 = blockIdx.y*128, n0 = blockIdx.x*64;
  const float* Ab = A + (size_t)blockIdx.z*sA;
  const float* Bb = B + (size_t)blockIdx.z*sB;
  float* Cb = C + (size_t)blockIdx.z*sC;
  int warp = tid>>5, lane = tid&31;
  int wm = (warp&3)*32, wn = (warp>>2)*32;
  int g = lane>>2, la3 = lane&3;
  float acc[2][4][4];
#pragma unroll
  for(int a=0;a<2;a++)
#pragma unroll
    for(int b=0;b<4;b++)
#pragma unroll
      for(int c=0;c<4;c++) acc[a][b][c]=0.f;

  for (int k0 = 0; k0 < K; k0 += 16) {
    __syncthreads();
#pragma unroll
    for (int q = 0; q < 2; ++q) {
      int idx = tid + q*256;
      if (MODE == 2) {
        int kr = idx >> 5, c4 = (idx & 31)*4;
        float4 v = *(const float4*)(Ab + (size_t)(k0+kr)*lda + m0 + c4);
        v.x = f2tf(v.x); v.y = f2tf(v.y); v.z = f2tf(v.z); v.w = f2tf(v.w);
        *(float4*)(As + kr*TFA + c4) = v;
      } else {
        int r = idx >> 2, c4 = (idx & 3)*4;
        float4 v = *(const float4*)(Ab + (size_t)(m0+r)*lda + k0 + c4);
        As[(c4+0)*TFA + r] = f2tf(v.x); As[(c4+1)*TFA + r] = f2tf(v.y);
        As[(c4+2)*TFA + r] = f2tf(v.z); As[(c4+3)*TFA + r] = f2tf(v.w);
      }
    }
    {
      int idx = tid;
      if (MODE == 0) {
        int r = idx >> 2, c4 = (idx & 3)*4;
        float4 v = *(const float4*)(Bb + (size_t)(n0+r)*ldb + k0 + c4);
        Bs[(c4+0)*TFB + r] = f2tf(v.x); Bs[(c4+1)*TFB + r] = f2tf(v.y);
        Bs[(c4+2)*TFB + r] = f2tf(v.z); Bs[(c4+3)*TFB + r] = f2tf(v.w);
      } else {
        int kr = idx >> 4, c4 = (idx & 15)*4;
        float4 v = *(const float4*)(Bb + (size_t)(k0+kr)*ldb + n0 + c4);
        v.x = f2tf(v.x); v.y = f2tf(v.y); v.z = f2tf(v.z); v.w = f2tf(v.w);
        *(float4*)(Bs + kr*TFB + c4) = v;
      }
    }
    __syncthreads();
#pragma unroll
    for (int ks = 0; ks < 2; ++ks) {
      int kb = ks*8;
      unsigned af[2][4];
#pragma unroll
      for (int mt = 0; mt < 2; ++mt) {
        const float* ap = As + (kb + la3)*TFA + wm + mt*16 + g;
        af[mt][0] = __float_as_uint(ap[0]);
        af[mt][1] = __float_as_uint(ap[8]);
        af[mt][2] = __float_as_uint(ap[4*TFA]);
        af[mt][3] = __float_as_uint(ap[4*TFA + 8]);
      }
#pragma unroll
      for (int nt = 0; nt < 4; ++nt) {
        const float* bp = Bs + (kb + la3)*TFB + wn + nt*8 + g;
        unsigned b0 = __float_as_uint(bp[0]);
        unsigned b1 = __float_as_uint(bp[4*TFB]);
#pragma unroll
        for (int mt = 0; mt < 2; ++mt) {
          asm volatile("mma.sync.aligned.m16n8k8.row.col.f32.tf32.tf32.f32 "
            "{%0,%1,%2,%3}, {%4,%5,%6,%7}, {%8,%9}, {%0,%1,%2,%3};"
            : "+f"(acc[mt][nt][0]), "+f"(acc[mt][nt][1]),
              "+f"(acc[mt][nt][2]), "+f"(acc[mt][nt][3])
            : "r"(af[mt][0]), "r"(af[mt][1]), "r"(af[mt][2]), "r"(af[mt][3]),
              "r"(b0), "r"(b1));
        }
      }
    }
  }
#pragma unroll
  for (int mt = 0; mt < 2; ++mt) {
    int mrow = m0 + wm + mt*16 + g;
#pragma unroll
    for (int nt = 0; nt < 4; ++nt) {
      int ncol = n0 + wn + nt*8 + la3*2;
      float b0v = 0.f, b1v = 0.f;
      if (bias) { b0v = bias[ncol]; b1v = bias[ncol+1]; }
      float v0 = acc[mt][nt][0] + b0v, v1 = acc[mt][nt][1] + b1v;
      float v2 = acc[mt][nt][2] + b0v, v3 = acc[mt][nt][3] + b1v;
      if (act == 2) {
        v0 = v0>=0.f?v0:0.01f*v0; v1 = v1>=0.f?v1:0.01f*v1;
        v2 = v2>=0.f?v2:0.01f*v2; v3 = v3>=0.f?v3:0.01f*v3;
      }
      *(float2*)(Cb + (size_t)mrow*ldc + ncol) = make_float2(v0, v1);
      *(float2*)(Cb + (size_t)(mrow+8)*ldc + ncol) = make_float2(v2, v3);
    }
  }
}

// ---------------- launch ----------------
extern "C" void kernel_launch(void* const* d_in, const int* in_sizes, int n_in,
                              void* d_out, int out_size) {
  (void)in_sizes; (void)n_in; (void)out_size;
  const float* x     = (const float*)d_in[0];
  const int*   seq   = (const int*)  d_in[1];
  const float* W_tp  = (const float*)d_in[2];
  const float* b_tp  = (const float*)d_in[3];
  const float* W_tc  = (const float*)d_in[4];
  const float* b_tc  = (const float*)d_in[5];
  const float* W_fij = (const float*)d_in[6];
  const float* w_root= (const float*)d_in[7];
  const float* r_emb = (const float*)d_in[8];
  const float* W_r   = (const float*)d_in[9];
  const float* b_r   = (const float*)d_in[10];
  const float* W_pc  = (const float*)d_in[11];
  const float* b_pc  = (const float*)d_in[12];
  float* out1 = (float*)d_out;
  float* out2 = out1 + (size_t)BT*SD;

  float *st,*se,*tp,*tc,*gg,*A,*L,*Li,*cat,*cat2;
  cudaGetSymbolAddress((void**)&st,   g_st);
  cudaGetSymbolAddress((void**)&se,   g_se);
  cudaGetSymbolAddress((void**)&tp,   g_tp);
  cudaGetSymbolAddress((void**)&tc,   g_tc);
  cudaGetSymbolAddress((void**)&gg,   g_gg);
  cudaGetSymbolAddress((void**)&A,    g_A);
  cudaGetSymbolAddress((void**)&L,    g_L);
  cudaGetSymbolAddress((void**)&Li,   g_Li);
  cudaGetSymbolAddress((void**)&cat,  g_cat);
  cudaGetSymbolAddress((void**)&cat2, g_cat2);

  const int PANEL_SMEM  = TT*33*4;              // 67584
  const int UPDATE_SMEM = TT*33*4 + NB*132*4;   // 84480
  cudaFuncSetAttribute(panel_k,  cudaFuncAttributeMaxDynamicSharedMemorySize, PANEL_SMEM);
  cudaFuncSetAttribute(update_k, cudaFuncAttributeMaxDynamicSharedMemorySize, UPDATE_SMEM);

  const long long sTT = (long long)TT*TT, sTS = (long long)TT*SD,
                  sTH = (long long)TT*HD, sP = (long long)TT1*TT;
  const float* pij = out2 + TT;   // rows 1..512 of each (513,512) batch slab

  split_k<<<BT*HD/256, 256>>>(x);
  gemm_k<0><<<dim3(4,256,1),256>>>(st, SD, 0, W_tp, SD, 0, tp, SD, 0, SD, b_tp, 1, 0);
  gemm_k<0><<<dim3(4,256,1),256>>>(st, SD, 0, W_tc, SD, 0, tc, SD, 0, SD, b_tc, 1, 0);
  gemm_k<1><<<dim3(4,256,1),256>>>(tp, SD, 0, W_fij, SD, 0, gg, SD, 0, SD, 0, 0, 0);
  gemm_k<0><<<dim3(8,8,BB),256>>>(gg, SD, sTS, tc, SD, sTS, A, TT, sTT, SD, 0, 3, seq);
  root_k<<<BT*32/256, 256>>>(w_root, seq);
  zcs_k<<<BT/1024, 1024>>>();
  colsum_k<<<dim3(8,BB), 512>>>();
  buildL_k<<<MT/256, 256>>>(seq);
  for (int kb = 0; kb < TT/NB; ++kb) {
    const float* s_ = (kb & 1) ? Li : L;
    float*       d_ = (kb & 1) ? L  : Li;
    panel_k<<<BB, 1024, PANEL_SMEM>>>(s_, d_, kb*NB);
    update_k<<<dim3(4, BB), 1024, UPDATE_SMEM>>>(s_, d_, kb*NB);
  }
  // 16 rounds (even count) -> final matrix in g_L; gather reads g_L, writes g_Li
  gather_k<<<dim3(4, BB), 1024>>>();
  diag_k<<<BB, TT>>>(out2);
  pij_k<<<dim3(16,16,BB), dim3(32,32)>>>(out2);
  tgemm_k<2><<<dim3(4,4,BB),256>>>(pij, TT, sP, se, SD, sTS, cat, HD, sTH, TT, 0, 0);
  addroot_k<<<MS/256, 256>>>(r_emb, out2);
  tgemm_k<1><<<dim3(4,4,BB),256>>>(pij, TT, sP, se, SD, sTS, cat + SD, HD, sTH, TT, 0, 0);
  tgemm_k<0><<<dim3(4,128,1),256>>>(cat, HD, 0, W_r, HD, 0, cat2, HD, 0, HD, b_r, 2);
  tgemm_k<1><<<dim3(4,4,BB),256>>>(pij, TT, sP, cat2, HD, sTH, cat2 + SD, HD, sTH, TT, 0, 0);
  tgemm_k<0><<<dim3(4,128,1),256>>>(cat2, HD, 0, W_pc, HD, 0, out1, SD, 0, HD, b_pc, 2);
}

// round 11
// speedup vs baseline: 1.3552x; 1.0099x over previous
#include <cuda_runtime.h>
#include <math.h>

#define BB 32
#define TT 512
#define TT1 513
#define SD 256
#define HD 512
#define BT (BB*TT)
#define MS (BT*SD)
#define MT (BT*TT)
#define NB 32

__device__ __align__(128) float g_st[MS], g_se[MS], g_tp[MS], g_tc[MS], g_gg[MS];
__device__ __align__(128) float g_A[MT], g_L[MT], g_Li[MT], g_cat[MT], g_cat2[MT];
__device__ __align__(128) float g_cs[BT], g_ar[BT], g_dg[BT];
__device__ __align__(128) int   g_piv[BT];
__device__ __align__(128) int   g_srcrow[BT];

// ---------------- elementwise ----------------
__global__ void split_k(const float* __restrict__ x) {
  int idx = blockIdx.x*blockDim.x + threadIdx.x;
  int c = idx & 511; int bt = idx >> 9;
  const float* xp = x + (size_t)bt*HD;
  if (c < SD) g_se[(size_t)bt*SD + c] = xp[c + ((c >= 128) ? 128 : 0)];
  else { int cc = c - SD; g_st[(size_t)bt*SD + cc] = xp[cc + 128 + ((cc >= 128) ? 128 : 0)]; }
}

__global__ void root_k(const float* __restrict__ wr, const int* __restrict__ seq) {
  int g = blockIdx.x*blockDim.x + threadIdx.x;
  int w = g >> 5, lane = g & 31;
  if (w >= BT) return;
  const float* s = g_st + (size_t)w*SD;
  float acc = 0.f;
  for (int c = lane; c < SD; c += 32) acc += s[c]*wr[c];
  for (int o = 16; o > 0; o >>= 1) acc += __shfl_down_sync(0xffffffffu, acc, o);
  if (lane == 0) {
    int b = w >> 9, t = w & 511;
    g_ar[w] = (t < seq[b]) ? expf(acc) : 0.0f;
  }
}

__global__ void zcs_k() {
  g_cs[blockIdx.x*1024 + threadIdx.x] = 0.0f;
}

__global__ void colsum_k() {
  int b = blockIdx.y, j = threadIdx.x;
  int i0 = blockIdx.x*64;
  const float* a = g_A + (size_t)b*TT*TT;
  float s = 0.f;
  #pragma unroll 8
  for (int i = i0; i < i0+64; ++i) s += a[(size_t)i*TT + j];
  atomicAdd(&g_cs[b*TT + j], s);
}

__global__ void buildL_k(const int* __restrict__ seq) {
  int idx = blockIdx.x*blockDim.x + threadIdx.x;
  int j = idx & 511, i = (idx >> 9) & 511, b = idx >> 18;
  float v;
  if (i == 0) v = g_ar[b*TT + j];
  else {
    v = -g_A[idx];
    if (i == j) v += g_cs[b*TT + j] + ((j >= seq[b]) ? 1.0f : 0.0f);
  }
  g_L[idx] = v;
}

// ---------------- blocked Gauss-Jordan inverse (NB=32, partial pivoting) ----------------
__global__ __launch_bounds__(1024) void panel_k(const float* __restrict__ srcM,
                                                float* __restrict__ dstM, int k0) {
  extern __shared__ float panel[];  // 512 x 33
  __shared__ float colM[TT];
  __shared__ int rowmap[TT];
  __shared__ float redv[32]; __shared__ int redi[32];
  __shared__ int sIr;
  int b = blockIdx.x, tid = threadIdx.x;
  const float* src = srcM + (size_t)b*TT*TT;
  float* dst = dstM + (size_t)b*TT*TT;
  for (int idx = tid; idx < TT*NB; idx += 1024) {
    int i = idx >> 5, c = idx & 31;
    panel[i*33+c] = src[(size_t)i*TT + k0 + c];
  }
  if (tid < TT) rowmap[tid] = tid;
  __syncthreads();
  for (int kk = 0; kk < NB; ++kk) {
    int k = k0 + kk;
    float v = -1.0f; int ix = tid;
    if (tid < TT && tid >= k) v = fabsf(panel[tid*33+kk]);
    for (int o = 16; o > 0; o >>= 1) {
      float v2 = __shfl_down_sync(0xffffffffu, v, o);
      int   i2 = __shfl_down_sync(0xffffffffu, ix, o);
      if (v2 > v) { v = v2; ix = i2; }
    }
    if ((tid & 31) == 0) { redv[tid>>5] = v; redi[tid>>5] = ix; }
    __syncthreads();
    if (tid < 32) {
      float bv = redv[tid]; int bi = redi[tid];
      for (int o = 16; o > 0; o >>= 1) {
        float v2 = __shfl_down_sync(0xffffffffu, bv, o);
        int   i2 = __shfl_down_sync(0xffffffffu, bi, o);
        if (v2 > bv) { bv = v2; bi = i2; }
      }
      if (tid == 0) { sIr = bi; g_piv[b*TT+k] = bi; }
    }
    __syncthreads();
    int ir = sIr;
    if (tid < NB) {
      if (ir != k) {
        float t = panel[k*33+tid]; panel[k*33+tid] = panel[ir*33+tid]; panel[ir*33+tid] = t;
      }
      if (tid == 0 && ir != k) { int t = rowmap[k]; rowmap[k] = rowmap[ir]; rowmap[ir] = t; }
    }
    __syncthreads();
    if (tid < NB) {
      float pv  = panel[k*33+kk];
      float val = panel[k*33+tid];
      __syncwarp();
      float pinv = 1.0f / pv;
      if (tid == kk) val = 1.0f;
      panel[k*33+tid] = val * pinv;
    } else if (tid >= 64 && tid < 64+TT) {
      colM[tid-64] = panel[(tid-64)*33+kk];
    }
    __syncthreads();
    {
      int c = tid & 31;
      float rk = panel[k*33+c];
      for (int idx = tid; idx < TT*NB; idx += 1024) {
        int i = idx >> 5;
        if (i == k) continue;
        float m = colM[i];
        float cur = (c == kk) ? 0.0f : panel[i*33+c];
        panel[i*33+c] = cur - m*rk;
      }
    }
    __syncthreads();
  }
  if (tid < TT) g_srcrow[b*TT + tid] = rowmap[tid];
  for (int idx = tid; idx < TT*NB; idx += 1024) {
    int i = idx >> 5, c = idx & 31;
    dst[(size_t)i*TT + k0 + c] = panel[i*33+c];
  }
}

__global__ __launch_bounds__(1024) void update_k(const float* __restrict__ srcM,
                                                 float* __restrict__ dstM, int k0) {
  extern __shared__ float sm[];
  float* Ps = sm;           // 512 x 33
  float* Rs = sm + TT*33;   // 32 x 132
  __shared__ int smap[TT];
  int b = blockIdx.y, tid = threadIdx.x;
  int jbase = blockIdx.x * 128;
  const float* src = srcM + (size_t)b*TT*TT;
  float* dst = dstM + (size_t)b*TT*TT;
  if (tid < TT) smap[tid] = g_srcrow[b*TT + tid];
  __syncthreads();
  for (int idx = tid; idx < TT*NB; idx += 1024) {
    int i = idx >> 5, c = idx & 31;
    Ps[i*33+c] = dst[(size_t)i*TT + k0 + c];
  }
  for (int idx = tid; idx < NB*128; idx += 1024) {
    int k = idx >> 7, c = idx & 127;
    Rs[k*132+c] = src[(size_t)smap[k0+k]*TT + jbase + c];
  }
  __syncthreads();
  int tx = tid & 31, ty = tid >> 5;
  int j = jbase + tx*4;
  if (j >= k0 && j < k0 + NB) return;
  for (int r = 0; r < 4; ++r) {
    int i0 = r*128 + ty*4;
    float acc[4][4] = {};
#pragma unroll 8
    for (int k = 0; k < NB; ++k) {
      float4 rv = *(const float4*)(Rs + k*132 + tx*4);
      float p0 = Ps[(i0+0)*33+k], p1 = Ps[(i0+1)*33+k];
      float p2 = Ps[(i0+2)*33+k], p3 = Ps[(i0+3)*33+k];
      acc[0][0]+=p0*rv.x; acc[0][1]+=p0*rv.y; acc[0][2]+=p0*rv.z; acc[0][3]+=p0*rv.w;
      acc[1][0]+=p1*rv.x; acc[1][1]+=p1*rv.y; acc[1][2]+=p1*rv.z; acc[1][3]+=p1*rv.w;
      acc[2][0]+=p2*rv.x; acc[2][1]+=p2*rv.y; acc[2][2]+=p2*rv.z; acc[2][3]+=p2*rv.w;
      acc[3][0]+=p3*rv.x; acc[3][1]+=p3*rv.y; acc[3][2]+=p3*rv.z; acc[3][3]+=p3*rv.w;
    }
#pragma unroll
    for (int q = 0; q < 4; ++q) {
      int i = i0 + q;
      float4 res;
      if (i >= k0 && i < k0 + NB) res = make_float4(0.f,0.f,0.f,0.f);
      else res = *(const float4*)(src + (size_t)smap[i]*TT + j);
      res.x += acc[q][0]; res.y += acc[q][1]; res.z += acc[q][2]; res.w += acc[q][3];
      *(float4*)(dst + (size_t)i*TT + j) = res;
    }
  }
}

__global__ __launch_bounds__(1024) void gather_k() {
  __shared__ int arr[TT];
  int b = blockIdx.y, tid = threadIdx.x;
  if (tid == 0) {
    for (int j = 0; j < TT; ++j) arr[j] = j;
    for (int l = TT-1; l >= 0; --l) {
      int p = g_piv[b*TT + l];
      if (p != l) { int t = arr[l]; arr[l] = arr[p]; arr[p] = t; }
    }
  }
  __syncthreads();
  const float* a = g_L + (size_t)b*TT*TT;
  float* o = g_Li + (size_t)b*TT*TT;
  int base = blockIdx.x * 128 * TT;
  for (int idx = tid; idx < 128*TT; idx += 1024) {
    int i = idx >> 9, j = idx & 511;
    o[base + idx] = a[(size_t)(blockIdx.x*128 + i)*TT + arr[j]];
  }
}

__global__ void diag_k(float* __restrict__ out2) {
  int b = blockIdx.x, j = threadIdx.x;
  const float* L = g_Li + (size_t)b*TT*TT;
  g_dg[b*TT + j] = L[(size_t)j*TT + j];
  out2[(size_t)b*TT1*TT + j] = g_ar[b*TT + j] * L[(size_t)j*TT];
}

__global__ __launch_bounds__(1024) void pij_k(float* __restrict__ out2) {
  __shared__ float Ts[32][33];
  int b = blockIdx.z;
  int i0 = blockIdx.y*32, j0 = blockIdx.x*32;
  int tx = threadIdx.x, ty = threadIdx.y;
  const float* L = g_Li + (size_t)b*TT*TT;
  Ts[ty][tx] = L[(size_t)(j0+ty)*TT + i0 + tx];
  __syncthreads();
  int i = i0 + ty, j = j0 + tx;
  float av  = g_A[(size_t)b*TT*TT + (size_t)i*TT + j];
  float dj  = (j > 0) ? g_dg[b*TT + j] : 0.0f;
  float lji = (i > 0) ? Ts[tx][ty] : 0.0f;
  out2[(size_t)b*TT1*TT + (size_t)(i+1)*TT + j] = av * (dj - lji);
}

__global__ void addroot_k(const float* __restrict__ re, const float* __restrict__ out2) {
  int idx = blockIdx.x*blockDim.x + threadIdx.x;
  int c = idx & 255, bi = idx >> 8;
  int b = bi >> 9, i = bi & 511;
  float pr = out2[(size_t)b*TT1*TT + i];
  g_cat[(size_t)bi*HD + c] += pr * re[c];
}

// ---------------- tf32 tensor-core GEMM ----------------
// MODE 0: C = A(MxK)*B(NxK)^T ; MODE 1: C = A(MxK)*B(KxN) ; MODE 2: C = A(KxM)^T*B(KxN)
// SPLIT=true: 3xTF32 (hi/lo split, ~fp32 accuracy). act: 0 none, 1 tanh, 2 leaky, 3 exp+mask
#define TFA 136
#define TFB 72
__device__ __forceinline__ float f2tf(float f) {
  unsigned u; asm("cvt.rna.tf32.f32 %0, %1;" : "=r"(u) : "f"(f));
  return __uint_as_float(u);
}
__device__ __forceinline__ void mma_tf32(float* d, const unsigned* a, unsigned b0, unsigned b1) {
  asm volatile("mma.sync.aligned.m16n8k8.row.col.f32.tf32.tf32.f32 "
    "{%0,%1,%2,%3}, {%4,%5,%6,%7}, {%8,%9}, {%0,%1,%2,%3};"
    : "+f"(d[0]), "+f"(d[1]), "+f"(d[2]), "+f"(d[3])
    : "r"(a[0]), "r"(a[1]), "r"(a[2]), "r"(a[3]), "r"(b0), "r"(b1));
}
template<int MODE, bool SPLIT>
__global__ __launch_bounds__(256)
void tgemm_k(const float* __restrict__ A, int lda, long long sA,
             const float* __restrict__ B, int ldb, long long sB,
             float* __restrict__ C, int ldc, long long sC,
             int K, const float* __restrict__ bias, int act, const int* __restrict__ seq)
{
  __shared__ __align__(16) float As[16*TFA];
  __shared__ __align__(16) float Bs[16*TFB];
  int tid = threadIdx.x;
  int m0 = blockIdx.y*128, n0 = blockIdx.x*64;
  const float* Ab = A + (size_t)blockIdx.z*sA;
  const float* Bb = B + (size_t)blockIdx.z*sB;
  float* Cb = C + (size_t)blockIdx.z*sC;
  int warp = tid>>5, lane = tid&31;
  int wm = (warp&3)*32, wn = (warp>>2)*32;
  int g = lane>>2, la3 = lane&3;
  float acc[2][4][4];
#pragma unroll
  for(int a=0;a<2;a++)
#pragma unroll
    for(int b=0;b<4;b++)
#pragma unroll
      for(int c=0;c<4;c++) acc[a][b][c]=0.f;

  for (int k0 = 0; k0 < K; k0 += 16) {
    __syncthreads();
#pragma unroll
    for (int q = 0; q < 2; ++q) {
      int idx = tid + q*256;
      if (MODE == 2) {
        int kr = idx >> 5, c4 = (idx & 31)*4;
        float4 v = *(const float4*)(Ab + (size_t)(k0+kr)*lda + m0 + c4);
        if (!SPLIT) { v.x = f2tf(v.x); v.y = f2tf(v.y); v.z = f2tf(v.z); v.w = f2tf(v.w); }
        *(float4*)(As + kr*TFA + c4) = v;
      } else {
        int r = idx >> 2, c4 = (idx & 3)*4;
        float4 v = *(const float4*)(Ab + (size_t)(m0+r)*lda + k0 + c4);
        if (!SPLIT) { v.x = f2tf(v.x); v.y = f2tf(v.y); v.z = f2tf(v.z); v.w = f2tf(v.w); }
        As[(c4+0)*TFA + r] = v.x; As[(c4+1)*TFA + r] = v.y;
        As[(c4+2)*TFA + r] = v.z; As[(c4+3)*TFA + r] = v.w;
      }
    }
    {
      int idx = tid;
      if (MODE == 0) {
        int r = idx >> 2, c4 = (idx & 3)*4;
        float4 v = *(const float4*)(Bb + (size_t)(n0+r)*ldb + k0 + c4);
        if (!SPLIT) { v.x = f2tf(v.x); v.y = f2tf(v.y); v.z = f2tf(v.z); v.w = f2tf(v.w); }
        Bs[(c4+0)*TFB + r] = v.x; Bs[(c4+1)*TFB + r] = v.y;
        Bs[(c4+2)*TFB + r] = v.z; Bs[(c4+3)*TFB + r] = v.w;
      } else {
        int kr = idx >> 4, c4 = (idx & 15)*4;
        float4 v = *(const float4*)(Bb + (size_t)(k0+kr)*ldb + n0 + c4);
        if (!SPLIT) { v.x = f2tf(v.x); v.y = f2tf(v.y); v.z = f2tf(v.z); v.w = f2tf(v.w); }
        *(float4*)(Bs + kr*TFB + c4) = v;
      }
    }
    __syncthreads();
#pragma unroll
    for (int ks = 0; ks < 2; ++ks) {
      int kb = ks*8;
      unsigned ah[2][4], al[2][4];
#pragma unroll
      for (int mt = 0; mt < 2; ++mt) {
        const float* ap = As + (kb + la3)*TFA + wm + mt*16 + g;
        float f0 = ap[0], f1 = ap[8], f2 = ap[4*TFA], f3 = ap[4*TFA + 8];
        if (SPLIT) {
          float h0 = f2tf(f0), h1 = f2tf(f1), h2 = f2tf(f2), h3 = f2tf(f3);
          ah[mt][0] = __float_as_uint(h0); al[mt][0] = __float_as_uint(f2tf(f0 - h0));
          ah[mt][1] = __float_as_uint(h1); al[mt][1] = __float_as_uint(f2tf(f1 - h1));
          ah[mt][2] = __float_as_uint(h2); al[mt][2] = __float_as_uint(f2tf(f2 - h2));
          ah[mt][3] = __float_as_uint(h3); al[mt][3] = __float_as_uint(f2tf(f3 - h3));
        } else {
          ah[mt][0] = __float_as_uint(f0); ah[mt][1] = __float_as_uint(f1);
          ah[mt][2] = __float_as_uint(f2); ah[mt][3] = __float_as_uint(f3);
        }
      }
#pragma unroll
      for (int nt = 0; nt < 4; ++nt) {
        const float* bp = Bs + (kb + la3)*TFB + wn + nt*8 + g;
        float bf0 = bp[0], bf1 = bp[4*TFB];
        unsigned bh0, bh1, bl0, bl1;
        if (SPLIT) {
          float h0 = f2tf(bf0), h1 = f2tf(bf1);
          bh0 = __float_as_uint(h0); bl0 = __float_as_uint(f2tf(bf0 - h0));
          bh1 = __float_as_uint(h1); bl1 = __float_as_uint(f2tf(bf1 - h1));
        } else {
          bh0 = __float_as_uint(bf0); bh1 = __float_as_uint(bf1);
          bl0 = bl1 = 0;
        }
#pragma unroll
        for (int mt = 0; mt < 2; ++mt) {
          mma_tf32(acc[mt][nt], ah[mt], bh0, bh1);
          if (SPLIT) {
            mma_tf32(acc[mt][nt], ah[mt], bl0, bl1);
            mma_tf32(acc[mt][nt], al[mt], bh0, bh1);
          }
        }
      }
    }
  }
  int len = (act == 3) ? seq[blockIdx.z] : 0;
#pragma unroll
  for (int mt = 0; mt < 2; ++mt) {
    int mrow = m0 + wm + mt*16 + g;
#pragma unroll
    for (int nt = 0; nt < 4; ++nt) {
      int ncol = n0 + wn + nt*8 + la3*2;
      float b0v = 0.f, b1v = 0.f;
      if (bias) { b0v = bias[ncol]; b1v = bias[ncol+1]; }
      float v[4] = { acc[mt][nt][0] + b0v, acc[mt][nt][1] + b1v,
                     acc[mt][nt][2] + b0v, acc[mt][nt][3] + b1v };
      if (act == 1) {
        v[0]=tanhf(v[0]); v[1]=tanhf(v[1]); v[2]=tanhf(v[2]); v[3]=tanhf(v[3]);
      } else if (act == 2) {
#pragma unroll
        for (int q = 0; q < 4; ++q) v[q] = v[q]>=0.f ? v[q] : 0.01f*v[q];
      } else if (act == 3) {
#pragma unroll
        for (int q = 0; q < 4; ++q) {
          int gi = mrow + (q >= 2 ? 8 : 0);
          int gj = ncol + (q & 1);
          v[q] = (gi != gj && gi < len && gj < len) ? expf(v[q]) : 0.0f;
        }
      }
      *(float2*)(Cb + (size_t)mrow*ldc + ncol) = make_float2(v[0], v[1]);
      *(float2*)(Cb + (size_t)(mrow+8)*ldc + ncol) = make_float2(v[2], v[3]);
    }
  }
}

// ---------------- launch ----------------
extern "C" void kernel_launch(void* const* d_in, const int* in_sizes, int n_in,
                              void* d_out, int out_size) {
  (void)in_sizes; (void)n_in; (void)out_size;
  const float* x     = (const float*)d_in[0];
  const int*   seq   = (const int*)  d_in[1];
  const float* W_tp  = (const float*)d_in[2];
  const float* b_tp  = (const float*)d_in[3];
  const float* W_tc  = (const float*)d_in[4];
  const float* b_tc  = (const float*)d_in[5];
  const float* W_fij = (const float*)d_in[6];
  const float* w_root= (const float*)d_in[7];
  const float* r_emb = (const float*)d_in[8];
  const float* W_r   = (const float*)d_in[9];
  const float* b_r   = (const float*)d_in[10];
  const float* W_pc  = (const float*)d_in[11];
  const float* b_pc  = (const float*)d_in[12];
  float* out1 = (float*)d_out;
  float* out2 = out1 + (size_t)BT*SD;

  float *st,*se,*tp,*tc,*gg,*A,*L,*Li,*cat,*cat2;
  cudaGetSymbolAddress((void**)&st,   g_st);
  cudaGetSymbolAddress((void**)&se,   g_se);
  cudaGetSymbolAddress((void**)&tp,   g_tp);
  cudaGetSymbolAddress((void**)&tc,   g_tc);
  cudaGetSymbolAddress((void**)&gg,   g_gg);
  cudaGetSymbolAddress((void**)&A,    g_A);
  cudaGetSymbolAddress((void**)&L,    g_L);
  cudaGetSymbolAddress((void**)&Li,   g_Li);
  cudaGetSymbolAddress((void**)&cat,  g_cat);
  cudaGetSymbolAddress((void**)&cat2, g_cat2);

  const int PANEL_SMEM  = TT*33*4;              // 67584
  const int UPDATE_SMEM = TT*33*4 + NB*132*4;   // 84480
  cudaFuncSetAttribute(panel_k,  cudaFuncAttributeMaxDynamicSharedMemorySize, PANEL_SMEM);
  cudaFuncSetAttribute(update_k, cudaFuncAttributeMaxDynamicSharedMemorySize, UPDATE_SMEM);

  const long long sTT = (long long)TT*TT, sTS = (long long)TT*SD,
                  sTH = (long long)TT*HD, sP = (long long)TT1*TT;
  const float* pij = out2 + TT;   // rows 1..512 of each (513,512) batch slab

  split_k<<<BT*HD/256, 256>>>(x);
  // tp = tanh(st @ W_tp^T + b) : split-tf32
  tgemm_k<0,true><<<dim3(4,128,1),256>>>(st, SD, 0, W_tp, SD, 0, tp, SD, 0, SD, b_tp, 1, 0);
  tgemm_k<0,true><<<dim3(4,128,1),256>>>(st, SD, 0, W_tc, SD, 0, tc, SD, 0, SD, b_tc, 1, 0);
  // gg = tp @ W_fij : split-tf32
  tgemm_k<1,true><<<dim3(4,128,1),256>>>(tp, SD, 0, W_fij, SD, 0, gg, SD, 0, SD, 0, 0, 0);
  // A = exp+mask( gg @ tc^T ) batched : split-tf32 with fused epilogue
  tgemm_k<0,true><<<dim3(8,4,BB),256>>>(gg, SD, sTS, tc, SD, sTS, A, TT, sTT, SD, 0, 3, seq);
  root_k<<<BT*32/256, 256>>>(w_root, seq);
  zcs_k<<<BT/1024, 1024>>>();
  colsum_k<<<dim3(8,BB), 512>>>();
  buildL_k<<<MT/256, 256>>>(seq);
  for (int kb = 0; kb < TT/NB; ++kb) {
    const float* s_ = (kb & 1) ? Li : L;
    float*       d_ = (kb & 1) ? L  : Li;
    panel_k<<<BB, 1024, PANEL_SMEM>>>(s_, d_, kb*NB);
    update_k<<<dim3(4, BB), 1024, UPDATE_SMEM>>>(s_, d_, kb*NB);
  }
  gather_k<<<dim3(4, BB), 1024>>>();
  diag_k<<<BB, TT>>>(out2);
  pij_k<<<dim3(16,16,BB), dim3(32,32)>>>(out2);
  tgemm_k<2,false><<<dim3(4,4,BB),256>>>(pij, TT, sP, se, SD, sTS, cat, HD, sTH, TT, 0, 0, 0);
  addroot_k<<<MS/256, 256>>>(r_emb, out2);
  tgemm_k<1,false><<<dim3(4,4,BB),256>>>(pij, TT, sP, se, SD, sTS, cat + SD, HD, sTH, TT, 0, 0, 0);
  tgemm_k<0,false><<<dim3(4,128,1),256>>>(cat, HD, 0, W_r, HD, 0, cat2, HD, 0, HD, b_r, 2, 0);
  tgemm_k<1,false><<<dim3(4,4,BB),256>>>(pij, TT, sP, cat2, HD, sTH, cat2 + SD, HD, sTH, TT, 0, 0, 0);
  tgemm_k<0,false><<<dim3(4,128,1),256>>>(cat2, HD, 0, W_pc, HD, 0, out1, SD, 0, HD, b_pc, 2, 0);
}